// round 1
// baseline (speedup 1.0000x reference)
#include <cuda_runtime.h>
#include <math.h>

#define T_STEPS 16
#define BATCH   32
#define NN      256
#define DD      128
#define HEADS   16
#define KGL     (HEADS*DD)   // 2048
#define GSTEPS  5
#define NCLS    2
#define SKIP    0.3f
#define EPSV    1e-8f

// ---------------- scratch (device globals; no allocation allowed) ------------
__device__ float g_V [(long)BATCH*NN*KGL];   // (B,N,H*D) normalized per-head vecs
__device__ float g_S [(long)BATCH*NN*NN];    // raw attention scores
__device__ float g_A0[(long)BATCH*NN*NN];    // adjacency ping
__device__ float g_A1[(long)BATCH*NN*NN];    // adjacency pong
__device__ float g_h0[(long)BATCH*NN*DD];
__device__ float g_h1[(long)BATCH*NN*DD];
__device__ float g_am[(long)BATCH*NN*DD];    // A @ h
__device__ float g_m [(long)BATCH*NN*DD];    // message
__device__ float g_r [(long)BATCH*NN*DD];
__device__ float g_z [(long)BATCH*NN*DD];

// ---------------- graph learner: V[b,n,h*D+d] = (x*w_h)/(||x*w_h||+eps)/sqrt(H)
__global__ __launch_bounds__(128) void norm_kernel(
    const float* __restrict__ x, const float* __restrict__ Wgl, float* __restrict__ V)
{
    long bn = blockIdx.x;            // b*N+n
    int d  = threadIdx.x;            // 0..127
    float xv = x[bn*DD + d];
    __shared__ float red[4];
    for (int h = 0; h < HEADS; h++) {
        float v = xv * Wgl[h*DD + d];
        float ss = v * v;
        #pragma unroll
        for (int o = 16; o; o >>= 1) ss += __shfl_xor_sync(0xffffffffu, ss, o);
        if ((d & 31) == 0) red[d >> 5] = ss;
        __syncthreads();
        float tot = red[0] + red[1] + red[2] + red[3];
        float scale = 0.25f / (sqrtf(tot) + EPSV);   // 0.25 = 1/sqrt(HEADS)
        V[bn*KGL + h*DD + d] = v * scale;
        __syncthreads();
    }
}

// ---------------- relu + row-normalize + skip blend --------------------------
__global__ __launch_bounds__(256) void blend_kernel(
    const float* __restrict__ S, const float* __restrict__ Aold, float* __restrict__ Anew)
{
    long row = blockIdx.x;           // b*N+n
    int m = threadIdx.x;             // 0..255
    float v = fmaxf(S[row*NN + m], 0.0f);
    float s = v;
    #pragma unroll
    for (int o = 16; o; o >>= 1) s += __shfl_xor_sync(0xffffffffu, s, o);
    __shared__ float sh[8];
    if ((m & 31) == 0) sh[m >> 5] = s;
    __syncthreads();
    float tot = sh[0]+sh[1]+sh[2]+sh[3]+sh[4]+sh[5]+sh[6]+sh[7];
    Anew[row*NN + m] = SKIP * Aold[row*NN + m] + (1.0f - SKIP) * v / (tot + EPSV);
}

// ---------------- generic fp32 tiled GEMM ------------------------------------
// C(M,N) = act( [A1 | A2(*A2m)](M,K) x B + bias )
//   BTRANS=0: B is (K,N) row-major.  BTRANS=1: B is (N,K) row-major (C = A B^T).
//   Split-K: columns [0,K1) come from A1 (lda=K1), [K1,K) from A2 (lda=K-K1),
//   optionally multiplied elementwise by A2m. K1 and K are multiples of 16.
//   EPI: 0 = acc(+bias); 1 = sigmoid(acc+bias); 2 = GRU: (1-z)*hold + z*tanh(acc+bias)
// All of M,N multiples of 64; K multiple of 16. No bounds checks.
#define BM 64
#define BN 64
#define BK 16

template<int BTRANS, int EPI>
__global__ __launch_bounds__(256) void gemm_k(
    const float* __restrict__ A1, const float* __restrict__ A2, const float* __restrict__ A2m,
    int K1,
    const float* __restrict__ Bmat, const float* __restrict__ bias,
    const float* __restrict__ Zg, const float* __restrict__ Hold,
    float* __restrict__ C,
    int M, int N, int K,
    long sA, long sB, long sC)
{
    __shared__ float As[BM][BK + 1];
    __shared__ float Bs[BK][BN + 1];

    const int bz = blockIdx.z;
    const float* A1b = A1 + (long)bz * sA;
    const float* A2b = A2 ? A2 : A1;   // never dereferenced unless K1 < K
    const float* Bb  = Bmat + (long)bz * sB;
    float*       Cb  = C + (long)bz * sC;

    const int tid = threadIdx.x;
    const int tx = tid & 15, ty = tid >> 4;
    const int rowBase = blockIdx.y * BM;
    const int colBase = blockIdx.x * BN;
    const int K2 = K - K1;

    float acc[4][4] = {};

    for (int kb = 0; kb < K; kb += BK) {
        // ---- load A tile (split source; 16-aligned so never straddles) ----
        const float* Asrc; int lda, kofs; bool isA2;
        if (kb < K1) { Asrc = A1b; lda = K1; kofs = kb;       isA2 = false; }
        else         { Asrc = A2b; lda = K2; kofs = kb - K1;  isA2 = true;  }
        #pragma unroll
        for (int i = 0; i < 4; i++) {
            int e = tid + i * 256;
            int r = e >> 4, c = e & 15;
            long gi = (long)(rowBase + r) * lda + kofs + c;
            float v = Asrc[gi];
            if (isA2 && A2m != nullptr) v *= A2m[gi];
            As[r][c] = v;
        }
        // ---- load B tile ----
        #pragma unroll
        for (int i = 0; i < 4; i++) {
            int e = tid + i * 256;
            if (BTRANS == 0) {
                int r = e >> 6, c = e & 63;
                Bs[r][c] = Bb[(long)(kb + r) * N + colBase + c];
            } else {
                int n = e >> 4, kk = e & 15;
                Bs[kk][n] = Bb[(long)(colBase + n) * K + kb + kk];
            }
        }
        __syncthreads();
        #pragma unroll
        for (int kk = 0; kk < BK; kk++) {
            float a[4], b[4];
            #pragma unroll
            for (int i = 0; i < 4; i++) a[i] = As[ty * 4 + i][kk];
            #pragma unroll
            for (int j = 0; j < 4; j++) b[j] = Bs[kk][tx * 4 + j];
            #pragma unroll
            for (int i = 0; i < 4; i++)
                #pragma unroll
                for (int j = 0; j < 4; j++)
                    acc[i][j] = fmaf(a[i], b[j], acc[i][j]);
        }
        __syncthreads();
    }

    #pragma unroll
    for (int i = 0; i < 4; i++) {
        int gm = rowBase + ty * 4 + i;
        #pragma unroll
        for (int j = 0; j < 4; j++) {
            int gn = colBase + tx * 4 + j;
            float v = acc[i][j];
            if (bias != nullptr) v += bias[gn];
            if (EPI == 1) {
                v = 1.0f / (1.0f + expf(-v));
            } else if (EPI == 2) {
                long idx = (long)gm * N + gn;
                float zv = Zg[idx];
                float ho = Hold[idx];
                v = (1.0f - zv) * ho + zv * tanhf(v);
            }
            Cb[(long)gm * N + gn] = v;
        }
    }
}

// ---------------- final classifier -------------------------------------------
__global__ __launch_bounds__(256) void fc_kernel(
    const float* __restrict__ h, const float* __restrict__ W,
    const float* __restrict__ bfc, float* __restrict__ out)
{
    int b = blockIdx.x, c = blockIdx.y;
    float s = 0.0f;
    for (int i = threadIdx.x; i < NN * DD; i += 256)
        s += h[(long)b * NN * DD + i] * W[(long)i * NCLS + c];
    #pragma unroll
    for (int o = 16; o; o >>= 1) s += __shfl_xor_sync(0xffffffffu, s, o);
    __shared__ float sh[8];
    if ((threadIdx.x & 31) == 0) sh[threadIdx.x >> 5] = s;
    __syncthreads();
    if (threadIdx.x == 0) {
        float t = 0.0f;
        for (int w = 0; w < 8; w++) t += sh[w];
        out[b * NCLS + c] = t + bfc[c];
    }
}

// ---------------- orchestration -----------------------------------------------
extern "C" void kernel_launch(void* const* d_in, const int* in_sizes, int n_in,
                              void* d_out, int out_size)
{
    const float* x        = (const float*)d_in[0];   // (T,B,N,D)
    const float* supports = (const float*)d_in[1];   // (B,N,N)
    const float* Wgl      = (const float*)d_in[2];   // (H,D)
    const float* Wa       = (const float*)d_in[3];   // (D,D)
    const float* ba       = (const float*)d_in[4];
    const float* Wr       = (const float*)d_in[5];   // (2D,D)
    const float* br       = (const float*)d_in[6];
    const float* Wz       = (const float*)d_in[7];
    const float* bz       = (const float*)d_in[8];
    const float* Wh       = (const float*)d_in[9];
    const float* bh       = (const float*)d_in[10];
    const float* Wfc      = (const float*)d_in[11];  // (N*D, C)
    const float* bfc      = (const float*)d_in[12];
    float* out            = (float*)d_out;

    float *V, *S, *A0, *A1b, *h0, *h1, *am, *mm, *rr, *zz;
    cudaGetSymbolAddress((void**)&V,  g_V);
    cudaGetSymbolAddress((void**)&S,  g_S);
    cudaGetSymbolAddress((void**)&A0, g_A0);
    cudaGetSymbolAddress((void**)&A1b,g_A1);
    cudaGetSymbolAddress((void**)&h0, g_h0);
    cudaGetSymbolAddress((void**)&h1, g_h1);
    cudaGetSymbolAddress((void**)&am, g_am);
    cudaGetSymbolAddress((void**)&mm, g_m);
    cudaGetSymbolAddress((void**)&rr, g_r);
    cudaGetSymbolAddress((void**)&zz, g_z);

    const long sBN  = (long)BATCH * NN;        // 8192 rows in flat GEMMs
    const float* Aold = supports;
    float* Anew = A0;
    const float* hp = nullptr;

    for (int t = 0; t < T_STEPS; t++) {
        const float* xt = x + (long)t * BATCH * NN * DD;

        // --- graph learner ---
        norm_kernel<<<BATCH * NN, 128>>>(xt, Wgl, V);
        // att scores: S[b] = V[b] @ V[b]^T   (256x256x2048, NT)
        gemm_k<1, 0><<<dim3(NN/BN, NN/BM, BATCH), 256>>>(
            V, nullptr, nullptr, KGL, V, nullptr, nullptr, nullptr, S,
            NN, NN, KGL, (long)NN*KGL, (long)NN*KGL, (long)NN*NN);
        blend_kernel<<<BATCH * NN, 256>>>(S, Aold, Anew);

        // --- GGNN: 5 GRU-gated propagation steps ---
        hp = xt;
        float* hn = h0;
        for (int s = 0; s < GSTEPS; s++) {
            // am = Anew @ hp      (batched 256x128x256, NN)
            gemm_k<0, 0><<<dim3(DD/BN, NN/BM, BATCH), 256>>>(
                Anew, nullptr, nullptr, NN, hp, nullptr, nullptr, nullptr, am,
                NN, DD, NN, (long)NN*NN, (long)NN*DD, (long)NN*DD);
            // m = am @ Wa + ba    (8192x128x128)
            gemm_k<0, 0><<<dim3(DD/BN, sBN/BM, 1), 256>>>(
                am, nullptr, nullptr, DD, Wa, ba, nullptr, nullptr, mm,
                (int)sBN, DD, DD, 0, 0, 0);
            // r = sigmoid([m|h] @ Wr + br)  (8192x128x256 split-K)
            gemm_k<0, 1><<<dim3(DD/BN, sBN/BM, 1), 256>>>(
                mm, hp, nullptr, DD, Wr, br, nullptr, nullptr, rr,
                (int)sBN, DD, 2*DD, 0, 0, 0);
            // z = sigmoid([m|h] @ Wz + bz)
            gemm_k<0, 1><<<dim3(DD/BN, sBN/BM, 1), 256>>>(
                mm, hp, nullptr, DD, Wz, bz, nullptr, nullptr, zz,
                (int)sBN, DD, 2*DD, 0, 0, 0);
            // h' = (1-z)*h + z*tanh([m | r*h] @ Wh + bh)
            gemm_k<0, 2><<<dim3(DD/BN, sBN/BM, 1), 256>>>(
                mm, hp, rr, DD, Wh, bh, zz, hp, hn,
                (int)sBN, DD, 2*DD, 0, 0, 0);
            hp = hn;
            hn = (hn == h0) ? h1 : h0;
        }

        // swap adjacency ping-pong
        Aold = Anew;
        Anew = (Anew == A0) ? A1b : A0;
    }

    // --- classifier on last timestep's h ---
    fc_kernel<<<dim3(BATCH, NCLS), 256>>>(hp, Wfc, bfc, out);
    (void)in_sizes; (void)n_in; (void)out_size;
}

// round 2
// speedup vs baseline: 2.6586x; 2.6586x over previous
#include <cuda_runtime.h>
#include <math.h>
#include <stdint.h>

#define T_STEPS 16
#define BATCH   32
#define NN      256
#define DD      128
#define HEADS   16
#define KGL     (HEADS*DD)
#define GSTEPS  5
#define NCLS    2
#define SKIPW   0.3f
#define EPSV    1e-8f

// ---------------- scratch (device globals; no allocation allowed) ------------
__device__ float g_S  [(long)BATCH*NN*NN];
__device__ float g_A0 [(long)BATCH*NN*NN];
__device__ float g_A1 [(long)BATCH*NN*NN];
__device__ float g_h0 [(long)BATCH*NN*DD];
__device__ float g_h1 [(long)BATCH*NN*DD];
__device__ float g_am [(long)BATCH*NN*DD];
__device__ float g_m  [(long)BATCH*NN*DD];
__device__ float g_rzb[(long)BATCH*NN*2*DD];
__device__ float g_ri [(long)BATCH*NN*HEADS];
__device__ float g_WaT [DD*DD];
__device__ float g_WrzT[2*DD*2*DD];
__device__ float g_WhT [DD*2*DD];
__device__ float g_brz [2*DD];

// ---------------- tf32 helpers ------------------------------------------------
__device__ __forceinline__ unsigned f2tf(float f) {
    unsigned u;
    asm("cvt.rna.tf32.f32 %0, %1;" : "=r"(u) : "f"(f));
    return u;
}
__device__ __forceinline__ uint4 cvt4(float4 v) {
    uint4 o; o.x = f2tf(v.x); o.y = f2tf(v.y); o.z = f2tf(v.z); o.w = f2tf(v.w);
    return o;
}
__device__ __forceinline__ void mma_tf32(float c[4], const unsigned a[4], const unsigned b[2]) {
    asm volatile(
        "mma.sync.aligned.m16n8k8.row.col.f32.tf32.tf32.f32 "
        "{%0,%1,%2,%3}, {%4,%5,%6,%7}, {%8,%9}, {%0,%1,%2,%3};\n"
        : "+f"(c[0]), "+f"(c[1]), "+f"(c[2]), "+f"(c[3])
        : "r"(a[0]), "r"(a[1]), "r"(a[2]), "r"(a[3]), "r"(b[0]), "r"(b[1]));
}

// ---------------- rinv: 0.25/(||x*w_h|| + eps) --------------------------------
__global__ __launch_bounds__(128) void rinv_kernel(
    const float* __restrict__ x, const float* __restrict__ Wgl, float* __restrict__ rinv)
{
    long bn = blockIdx.x;
    int d = threadIdx.x;
    float xv = x[bn * DD + d];
    __shared__ float red[4];
    for (int h = 0; h < HEADS; h++) {
        float v = xv * Wgl[h * DD + d];
        float ss = v * v;
        #pragma unroll
        for (int o = 16; o; o >>= 1) ss += __shfl_xor_sync(0xffffffffu, ss, o);
        if ((d & 31) == 0) red[d >> 5] = ss;
        __syncthreads();
        if (d == 0) {
            float tot = red[0] + red[1] + red[2] + red[3];
            rinv[bn * HEADS + h] = 0.25f / (sqrtf(tot) + EPSV);
        }
        __syncthreads();
    }
}

// ---------------- relu + row-normalize + skip blend ---------------------------
__global__ __launch_bounds__(256) void blend_kernel(
    const float* __restrict__ S, const float* __restrict__ Aold, float* __restrict__ Anew)
{
    long row = blockIdx.x;
    int m = threadIdx.x;
    float v = fmaxf(S[row * NN + m], 0.0f);
    float s = v;
    #pragma unroll
    for (int o = 16; o; o >>= 1) s += __shfl_xor_sync(0xffffffffu, s, o);
    __shared__ float sh[8];
    if ((m & 31) == 0) sh[m >> 5] = s;
    __syncthreads();
    float tot = sh[0]+sh[1]+sh[2]+sh[3]+sh[4]+sh[5]+sh[6]+sh[7];
    Anew[row * NN + m] = SKIPW * Aold[row * NN + m] + (1.0f - SKIPW) * v / (tot + EPSV);
}

// ---------------- weight pre-transpose ----------------------------------------
__global__ void prep_kernel(
    const float* __restrict__ Wa, const float* __restrict__ Wr,
    const float* __restrict__ Wz, const float* __restrict__ Wh,
    const float* __restrict__ br, const float* __restrict__ bz,
    float* __restrict__ WaT, float* __restrict__ WrzT,
    float* __restrict__ WhT, float* __restrict__ brz)
{
    for (int idx = blockIdx.x * blockDim.x + threadIdx.x; idx < 65536;
         idx += gridDim.x * blockDim.x) {
        if (idx < 16384) { int n = idx >> 7, k = idx & 127; WaT[n*128 + k] = Wa[k*128 + n]; }
        {   int n = idx >> 8, k = idx & 255;   // 256 x 256
            WrzT[n*256 + k] = (n < 128) ? Wr[k*128 + n] : Wz[k*128 + (n-128)]; }
        if (idx < 32768) { int n = idx >> 8, k = idx & 255; WhT[n*256 + k] = Wh[k*128 + n]; }
        if (idx < 256)   { brz[idx] = (idx < 128) ? br[idx] : bz[idx - 128]; }
    }
}

// ---------------- tf32 tensor-core GEMM ---------------------------------------
// CTA tile 128x64, BK=32, 128 threads (4 warps, 2x2, warp tile 64x32).
// ASRC: 0 = dense/split ([A1|A2], A2 optionally * A2m), 2 = virtual V (attention)
// BMODE: 0 = B is (K,N) row-major (transpose on load), 1 = B is (N,K) row-major,
//        2 = virtual V (attention NT)
// EPI: 0 = (+bias); 1 = sigmoid(+bias); 2 = GRU: (1-z)*hold + z*tanh(+bias)
template<int ASRC, int BMODE, int EPI>
__global__ __launch_bounds__(128) void tgemm(
    const float* __restrict__ A1, const float* __restrict__ A2,
    const float* __restrict__ A2m, int ldm, int K1,
    const float* __restrict__ Bmat, int ldb,
    const float* __restrict__ bias,
    const float* __restrict__ Zbuf, int ldz, int zoff,
    const float* __restrict__ Hold, int ldh,
    float* __restrict__ C, int ldc,
    int K,
    long sA, long sB, long sC,
    const float* __restrict__ xatt, const float* __restrict__ Wgl,
    const float* __restrict__ rinv)
{
    __shared__ __align__(16) unsigned As[128][36];
    __shared__ __align__(16) unsigned Bs[64][36];

    const int tid = threadIdx.x;
    const int lane = tid & 31, wid = tid >> 5;
    const int wr = (wid >> 1) * 64;
    const int wc = (wid & 1) * 32;
    const int g = lane >> 2, t4 = lane & 3;

    const int bz_ = blockIdx.z;
    const int rowBase = blockIdx.y * 128;
    const int colBase = blockIdx.x * 64;

    const float* A1b = A1 + (long)bz_ * sA;
    const float* Bb  = Bmat + (long)bz_ * sB;
    float*       Cb  = C + (long)bz_ * sC;
    const float* xb    = xatt ? xatt + (long)bz_ * NN * DD : nullptr;
    const float* rinvb = rinv ? rinv + (long)bz_ * NN * HEADS : nullptr;

    float acc[4][4][4] = {};

    for (int kb = 0; kb < K; kb += 32) {
        // ---------- A tile (128 x 32) ----------
        if (ASRC == 2) {
            #pragma unroll
            for (int it = 0; it < 8; it++) {
                int e = tid + it * 128;
                int r = e >> 3, c4 = e & 7;
                int kglob = kb + c4 * 4;
                int h = kglob >> 7;
                int node = rowBase + r;
                float4 xv = *(const float4*)&xb[(long)node * DD + (kglob & 127)];
                float4 wv = *(const float4*)&Wgl[kglob];
                float rn = rinvb[node * HEADS + h];
                float4 v = make_float4(xv.x*wv.x*rn, xv.y*wv.y*rn, xv.z*wv.z*rn, xv.w*wv.w*rn);
                *(uint4*)&As[r][c4 * 4] = cvt4(v);
            }
        } else {
            const float* Asrc; int lda_, kofs; bool mult;
            if (kb < K1) { Asrc = A1b; lda_ = K1;     kofs = kb;       mult = false; }
            else         { Asrc = A2;  lda_ = K - K1; kofs = kb - K1;  mult = (A2m != nullptr); }
            #pragma unroll
            for (int it = 0; it < 8; it++) {
                int e = tid + it * 128;
                int r = e >> 3, c4 = e & 7;
                float4 v = *(const float4*)&Asrc[(long)(rowBase + r) * lda_ + kofs + c4 * 4];
                if (mult) {
                    float4 mv = *(const float4*)&A2m[(long)(rowBase + r) * ldm + kofs + c4 * 4];
                    v.x *= mv.x; v.y *= mv.y; v.z *= mv.z; v.w *= mv.w;
                }
                *(uint4*)&As[r][c4 * 4] = cvt4(v);
            }
        }
        // ---------- B tile (64 x 32, stored n-major) ----------
        if (BMODE == 2) {
            #pragma unroll
            for (int it = 0; it < 4; it++) {
                int e = tid + it * 128;
                int n = e >> 3, c4 = e & 7;
                int kglob = kb + c4 * 4;
                int h = kglob >> 7;
                int node = colBase + n;
                float4 xv = *(const float4*)&xb[(long)node * DD + (kglob & 127)];
                float4 wv = *(const float4*)&Wgl[kglob];
                float rn = rinvb[node * HEADS + h];
                float4 v = make_float4(xv.x*wv.x*rn, xv.y*wv.y*rn, xv.z*wv.z*rn, xv.w*wv.w*rn);
                *(uint4*)&Bs[n][c4 * 4] = cvt4(v);
            }
        } else if (BMODE == 1) {
            #pragma unroll
            for (int it = 0; it < 4; it++) {
                int e = tid + it * 128;
                int n = e >> 3, c4 = e & 7;
                float4 v = *(const float4*)&Bb[(long)(colBase + n) * ldb + kb + c4 * 4];
                *(uint4*)&Bs[n][c4 * 4] = cvt4(v);
            }
        } else {
            #pragma unroll
            for (int it = 0; it < 4; it++) {
                int e = tid + it * 128;
                int kk = e & 31, n4 = e >> 5;
                float4 v = *(const float4*)&Bb[(long)(kb + kk) * ldb + colBase + n4 * 4];
                Bs[n4*4 + 0][kk] = f2tf(v.x);
                Bs[n4*4 + 1][kk] = f2tf(v.y);
                Bs[n4*4 + 2][kk] = f2tf(v.z);
                Bs[n4*4 + 3][kk] = f2tf(v.w);
            }
        }
        __syncthreads();

        #pragma unroll
        for (int k8 = 0; k8 < 32; k8 += 8) {
            unsigned af[4][4], bf[4][2];
            #pragma unroll
            for (int i = 0; i < 4; i++) {
                int r = wr + i * 16 + g;
                af[i][0] = As[r    ][k8 + t4];
                af[i][1] = As[r + 8][k8 + t4];
                af[i][2] = As[r    ][k8 + t4 + 4];
                af[i][3] = As[r + 8][k8 + t4 + 4];
            }
            #pragma unroll
            for (int j = 0; j < 4; j++) {
                int n = wc + j * 8 + g;
                bf[j][0] = Bs[n][k8 + t4];
                bf[j][1] = Bs[n][k8 + t4 + 4];
            }
            #pragma unroll
            for (int i = 0; i < 4; i++)
                #pragma unroll
                for (int j = 0; j < 4; j++)
                    mma_tf32(acc[i][j], af[i], bf[j]);
        }
        __syncthreads();
    }

    // ---------- epilogue ----------
    #pragma unroll
    for (int i = 0; i < 4; i++) {
        int r0 = rowBase + wr + i * 16 + g;
        int r1 = r0 + 8;
        #pragma unroll
        for (int j = 0; j < 4; j++) {
            int c0 = colBase + wc + j * 8 + t4 * 2;
            float v00 = acc[i][j][0], v01 = acc[i][j][1];
            float v10 = acc[i][j][2], v11 = acc[i][j][3];
            if (bias != nullptr) {
                float b0 = bias[c0], b1 = bias[c0 + 1];
                v00 += b0; v01 += b1; v10 += b0; v11 += b1;
            }
            if (EPI == 1) {
                v00 = 1.0f / (1.0f + expf(-v00));
                v01 = 1.0f / (1.0f + expf(-v01));
                v10 = 1.0f / (1.0f + expf(-v10));
                v11 = 1.0f / (1.0f + expf(-v11));
            } else if (EPI == 2) {
                float z00 = Zbuf[(long)r0 * ldz + zoff + c0];
                float z01 = Zbuf[(long)r0 * ldz + zoff + c0 + 1];
                float z10 = Zbuf[(long)r1 * ldz + zoff + c0];
                float z11 = Zbuf[(long)r1 * ldz + zoff + c0 + 1];
                float h00 = Hold[(long)r0 * ldh + c0];
                float h01 = Hold[(long)r0 * ldh + c0 + 1];
                float h10 = Hold[(long)r1 * ldh + c0];
                float h11 = Hold[(long)r1 * ldh + c0 + 1];
                v00 = (1.0f - z00) * h00 + z00 * tanhf(v00);
                v01 = (1.0f - z01) * h01 + z01 * tanhf(v01);
                v10 = (1.0f - z10) * h10 + z10 * tanhf(v10);
                v11 = (1.0f - z11) * h11 + z11 * tanhf(v11);
            }
            *(float2*)&Cb[(long)r0 * ldc + c0] = make_float2(v00, v01);
            *(float2*)&Cb[(long)r1 * ldc + c0] = make_float2(v10, v11);
        }
    }
}

// ---------------- final classifier --------------------------------------------
__global__ __launch_bounds__(256) void fc_kernel(
    const float* __restrict__ h, const float* __restrict__ W,
    const float* __restrict__ bfc, float* __restrict__ out)
{
    int b = blockIdx.x, c = blockIdx.y;
    float s = 0.0f;
    for (int i = threadIdx.x; i < NN * DD; i += 256)
        s += h[(long)b * NN * DD + i] * W[(long)i * NCLS + c];
    #pragma unroll
    for (int o = 16; o; o >>= 1) s += __shfl_xor_sync(0xffffffffu, s, o);
    __shared__ float sh[8];
    if ((threadIdx.x & 31) == 0) sh[threadIdx.x >> 5] = s;
    __syncthreads();
    if (threadIdx.x == 0) {
        float t = 0.0f;
        for (int w = 0; w < 8; w++) t += sh[w];
        out[b * NCLS + c] = t + bfc[c];
    }
}

// ---------------- orchestration -----------------------------------------------
extern "C" void kernel_launch(void* const* d_in, const int* in_sizes, int n_in,
                              void* d_out, int out_size)
{
    const float* x        = (const float*)d_in[0];
    const float* supports = (const float*)d_in[1];
    const float* Wgl      = (const float*)d_in[2];
    const float* Wa       = (const float*)d_in[3];
    const float* ba       = (const float*)d_in[4];
    const float* Wr       = (const float*)d_in[5];
    const float* br       = (const float*)d_in[6];
    const float* Wz       = (const float*)d_in[7];
    const float* bz       = (const float*)d_in[8];
    const float* Wh       = (const float*)d_in[9];
    const float* bh       = (const float*)d_in[10];
    const float* Wfc      = (const float*)d_in[11];
    const float* bfc      = (const float*)d_in[12];
    float* out            = (float*)d_out;

    float *S, *A0, *A1b, *h0, *h1, *am, *mm, *rz, *ri;
    float *WaT, *WrzT, *WhT, *brz;
    cudaGetSymbolAddress((void**)&S,   g_S);
    cudaGetSymbolAddress((void**)&A0,  g_A0);
    cudaGetSymbolAddress((void**)&A1b, g_A1);
    cudaGetSymbolAddress((void**)&h0,  g_h0);
    cudaGetSymbolAddress((void**)&h1,  g_h1);
    cudaGetSymbolAddress((void**)&am,  g_am);
    cudaGetSymbolAddress((void**)&mm,  g_m);
    cudaGetSymbolAddress((void**)&rz,  g_rzb);
    cudaGetSymbolAddress((void**)&ri,  g_ri);
    cudaGetSymbolAddress((void**)&WaT,  g_WaT);
    cudaGetSymbolAddress((void**)&WrzT, g_WrzT);
    cudaGetSymbolAddress((void**)&WhT,  g_WhT);
    cudaGetSymbolAddress((void**)&brz,  g_brz);

    prep_kernel<<<64, 256>>>(Wa, Wr, Wz, Wh, br, bz, WaT, WrzT, WhT, brz);

    const float* Aold = supports;
    float* Anew = A0;
    const float* hp = nullptr;

    for (int t = 0; t < T_STEPS; t++) {
        const float* xt = x + (long)t * BATCH * NN * DD;

        // ---- graph learner: rinv, virtual-V NT GEMM, blend ----
        rinv_kernel<<<BATCH * NN, 128>>>(xt, Wgl, ri);
        tgemm<2, 2, 0><<<dim3(4, 2, BATCH), 128>>>(
            nullptr, nullptr, nullptr, 0, KGL,
            nullptr, 0, nullptr, nullptr, 0, 0, nullptr, 0,
            S, NN, KGL, 0, 0, (long)NN * NN, xt, Wgl, ri);
        blend_kernel<<<BATCH * NN, 256>>>(S, Aold, Anew);

        // ---- GGNN propagation ----
        hp = xt;
        float* hn = h0;
        for (int s = 0; s < GSTEPS; s++) {
            // am = Anew @ h          (batched 256x128, K=256)
            tgemm<0, 0, 0><<<dim3(2, 2, BATCH), 128>>>(
                Anew, nullptr, nullptr, 0, NN,
                hp, DD, nullptr, nullptr, 0, 0, nullptr, 0,
                am, DD, NN, (long)NN * NN, (long)NN * DD, (long)NN * DD,
                nullptr, nullptr, nullptr);
            // m = am @ Wa + ba       (8192x128, K=128)
            tgemm<0, 1, 0><<<dim3(2, 64, 1), 128>>>(
                am, nullptr, nullptr, 0, DD,
                WaT, DD, ba, nullptr, 0, 0, nullptr, 0,
                mm, DD, DD, 0, 0, 0, nullptr, nullptr, nullptr);
            // [r|z] = sigmoid([m|h] @ [Wr|Wz] + [br|bz])  (8192x256, K=256)
            tgemm<0, 1, 1><<<dim3(4, 64, 1), 128>>>(
                mm, hp, nullptr, 0, DD,
                WrzT, 2 * DD, brz, nullptr, 0, 0, nullptr, 0,
                rz, 2 * DD, 2 * DD, 0, 0, 0, nullptr, nullptr, nullptr);
            // h' = (1-z)h + z*tanh([m | r*h] @ Wh + bh)   (8192x128, K=256)
            tgemm<0, 1, 2><<<dim3(2, 64, 1), 128>>>(
                mm, hp, rz, 2 * DD, DD,
                WhT, 2 * DD, bh, rz, 2 * DD, DD, hp, DD,
                hn, DD, 2 * DD, 0, 0, 0, nullptr, nullptr, nullptr);
            hp = hn;
            hn = (hn == h0) ? h1 : h0;
        }

        Aold = Anew;
        Anew = (Anew == A0) ? A1b : A0;
    }

    fc_kernel<<<dim3(BATCH, NCLS), 256>>>(hp, Wfc, bfc, out);
    (void)in_sizes; (void)n_in; (void)out_size;
}

// round 3
// speedup vs baseline: 10.1705x; 3.8255x over previous
#include <cuda_runtime.h>
#include <math.h>
#include <stdint.h>

#define T_STEPS 16
#define BATCH   32
#define NN      256
#define DD      128
#define HEADS   16
#define KGL     (HEADS*DD)
#define GSTEPS  5
#define NCLS    2
#define SKIPW   0.3f
#define EPSV    1e-8f

// ---------------- scratch (device globals; no allocation allowed) ------------
__device__ float g_S  [(long)T_STEPS*BATCH*NN*NN];   // raw scores, all t (134MB)
__device__ float g_A0 [(long)BATCH*NN*NN];           // A_final
__device__ float g_h0 [(long)BATCH*NN*DD];
__device__ float g_h1 [(long)BATCH*NN*DD];
__device__ float g_am [(long)BATCH*NN*DD];
__device__ float g_m  [(long)BATCH*NN*DD];
__device__ float g_rzb[(long)BATCH*NN*2*DD];
__device__ float g_ri [(long)T_STEPS*BATCH*NN*HEADS];
__device__ float g_WaT [DD*DD];
__device__ float g_WrzT[2*DD*2*DD];
__device__ float g_WhT [DD*2*DD];
__device__ float g_brz [2*DD];

// ---------------- tf32 helpers ------------------------------------------------
__device__ __forceinline__ unsigned f2tf(float f) {
    unsigned u;
    asm("cvt.rna.tf32.f32 %0, %1;" : "=r"(u) : "f"(f));
    return u;
}
__device__ __forceinline__ uint4 cvt4(float4 v) {
    uint4 o; o.x = f2tf(v.x); o.y = f2tf(v.y); o.z = f2tf(v.z); o.w = f2tf(v.w);
    return o;
}
__device__ __forceinline__ void mma_tf32(float c[4], const unsigned a[4], const unsigned b[2]) {
    asm volatile(
        "mma.sync.aligned.m16n8k8.row.col.f32.tf32.tf32.f32 "
        "{%0,%1,%2,%3}, {%4,%5,%6,%7}, {%8,%9}, {%0,%1,%2,%3};\n"
        : "+f"(c[0]), "+f"(c[1]), "+f"(c[2]), "+f"(c[3])
        : "r"(a[0]), "r"(a[1]), "r"(a[2]), "r"(a[3]), "r"(b[0]), "r"(b[1]));
}

// ---------------- rinv for ALL timesteps: 0.25/(||x*w_h|| + eps) ---------------
__global__ __launch_bounds__(128) void rinv_kernel(
    const float* __restrict__ x, const float* __restrict__ Wgl, float* __restrict__ rinv)
{
    long bn = blockIdx.x;            // flat over T*B*N
    int d = threadIdx.x;
    float xv = x[bn * DD + d];
    __shared__ float red[4];
    for (int h = 0; h < HEADS; h++) {
        float v = xv * Wgl[h * DD + d];
        float ss = v * v;
        #pragma unroll
        for (int o = 16; o; o >>= 1) ss += __shfl_xor_sync(0xffffffffu, ss, o);
        if ((d & 31) == 0) red[d >> 5] = ss;
        __syncthreads();
        if (d == 0) {
            float tot = red[0] + red[1] + red[2] + red[3];
            rinv[bn * HEADS + h] = 0.25f / (sqrtf(tot) + EPSV);
        }
        __syncthreads();
    }
}

// ------- fused relu + row-normalize + geometric-weighted accumulate -> A_15 ----
// A_15 = 0.3^16 * supports + 0.7 * sum_t 0.3^(15-t) * rownorm(relu(S_t))
__global__ __launch_bounds__(256) void blend_all_kernel(
    const float* __restrict__ S, const float* __restrict__ sup, float* __restrict__ A)
{
    int row = blockIdx.x;            // b*NN + n
    int b = row >> 8, n = row & 255;
    int m = threadIdx.x;
    __shared__ float sh[8];

    float w[T_STEPS];
    float wt = 1.0f - SKIPW;
    for (int t = T_STEPS - 1; t >= 0; t--) { w[t] = wt; wt *= SKIPW; }

    float acc = powf(SKIPW, (float)T_STEPS) * sup[(long)row * NN + m];

    for (int t = 0; t < T_STEPS; t++) {
        long idx = (((long)t * BATCH + b) * NN + n) * NN + m;
        float v = fmaxf(S[idx], 0.0f);
        float s = v;
        #pragma unroll
        for (int o = 16; o; o >>= 1) s += __shfl_xor_sync(0xffffffffu, s, o);
        if ((m & 31) == 0) sh[m >> 5] = s;
        __syncthreads();
        float tot = sh[0]+sh[1]+sh[2]+sh[3]+sh[4]+sh[5]+sh[6]+sh[7];
        acc += w[t] * v / (tot + EPSV);
        __syncthreads();
    }
    A[(long)row * NN + m] = acc;
}

// ---------------- weight pre-transpose ----------------------------------------
__global__ void prep_kernel(
    const float* __restrict__ Wa, const float* __restrict__ Wr,
    const float* __restrict__ Wz, const float* __restrict__ Wh,
    const float* __restrict__ br, const float* __restrict__ bz,
    float* __restrict__ WaT, float* __restrict__ WrzT,
    float* __restrict__ WhT, float* __restrict__ brz)
{
    for (int idx = blockIdx.x * blockDim.x + threadIdx.x; idx < 65536;
         idx += gridDim.x * blockDim.x) {
        if (idx < 16384) { int n = idx >> 7, k = idx & 127; WaT[n*128 + k] = Wa[k*128 + n]; }
        {   int n = idx >> 8, k = idx & 255;
            WrzT[n*256 + k] = (n < 128) ? Wr[k*128 + n] : Wz[k*128 + (n-128)]; }
        if (idx < 32768) { int n = idx >> 8, k = idx & 255; WhT[n*256 + k] = Wh[k*128 + n]; }
        if (idx < 256)   { brz[idx] = (idx < 128) ? br[idx] : bz[idx - 128]; }
    }
}

// ---------------- tf32 tensor-core GEMM ---------------------------------------
// CTA tile 128x64, BK=32, 128 threads (4 warps 2x2, warp tile 64x32).
// ASRC: 0 = dense/split ([A1|A2], A2 optionally * A2m), 2 = virtual V (attention)
// BMODE: 0 = B (K,N) row-major; 1 = B (N,K) row-major; 2 = virtual V (attention)
// EPI: 0 = (+bias); 1 = sigmoid(+bias); 2 = GRU
template<int ASRC, int BMODE, int EPI>
__global__ __launch_bounds__(128) void tgemm(
    const float* __restrict__ A1, const float* __restrict__ A2,
    const float* __restrict__ A2m, int ldm, int K1,
    const float* __restrict__ Bmat, int ldb,
    const float* __restrict__ bias,
    const float* __restrict__ Zbuf, int ldz, int zoff,
    const float* __restrict__ Hold, int ldh,
    float* __restrict__ C, int ldc,
    int K,
    long sA, long sB, long sC,
    const float* __restrict__ xatt, const float* __restrict__ Wgl,
    const float* __restrict__ rinv)
{
    __shared__ __align__(16) unsigned As[128][36];
    __shared__ __align__(16) unsigned Bs[64][36];

    const int tid = threadIdx.x;
    const int lane = tid & 31, wid = tid >> 5;
    const int wr = (wid >> 1) * 64;
    const int wc = (wid & 1) * 32;
    const int g = lane >> 2, t4 = lane & 3;

    const int bz_ = blockIdx.z;
    const int rowBase = blockIdx.y * 128;
    const int colBase = blockIdx.x * 64;

    const float* A1b = A1 + (long)bz_ * sA;
    const float* Bb  = Bmat + (long)bz_ * sB;
    float*       Cb  = C + (long)bz_ * sC;
    const float* xb    = xatt ? xatt + (long)bz_ * NN * DD : nullptr;
    const float* rinvb = rinv ? rinv + (long)bz_ * NN * HEADS : nullptr;

    float acc[4][4][4] = {};

    for (int kb = 0; kb < K; kb += 32) {
        if (ASRC == 2) {
            #pragma unroll
            for (int it = 0; it < 8; it++) {
                int e = tid + it * 128;
                int r = e >> 3, c4 = e & 7;
                int kglob = kb + c4 * 4;
                int h = kglob >> 7;
                int node = rowBase + r;
                float4 xv = *(const float4*)&xb[(long)node * DD + (kglob & 127)];
                float4 wv = *(const float4*)&Wgl[kglob];
                float rn = rinvb[node * HEADS + h];
                float4 v = make_float4(xv.x*wv.x*rn, xv.y*wv.y*rn, xv.z*wv.z*rn, xv.w*wv.w*rn);
                *(uint4*)&As[r][c4 * 4] = cvt4(v);
            }
        } else {
            const float* Asrc; int lda_, kofs; bool mult;
            if (kb < K1) { Asrc = A1b; lda_ = K1;     kofs = kb;       mult = false; }
            else         { Asrc = A2;  lda_ = K - K1; kofs = kb - K1;  mult = (A2m != nullptr); }
            #pragma unroll
            for (int it = 0; it < 8; it++) {
                int e = tid + it * 128;
                int r = e >> 3, c4 = e & 7;
                float4 v = *(const float4*)&Asrc[(long)(rowBase + r) * lda_ + kofs + c4 * 4];
                if (mult) {
                    float4 mv = *(const float4*)&A2m[(long)(rowBase + r) * ldm + kofs + c4 * 4];
                    v.x *= mv.x; v.y *= mv.y; v.z *= mv.z; v.w *= mv.w;
                }
                *(uint4*)&As[r][c4 * 4] = cvt4(v);
            }
        }
        if (BMODE == 2) {
            #pragma unroll
            for (int it = 0; it < 4; it++) {
                int e = tid + it * 128;
                int n = e >> 3, c4 = e & 7;
                int kglob = kb + c4 * 4;
                int h = kglob >> 7;
                int node = colBase + n;
                float4 xv = *(const float4*)&xb[(long)node * DD + (kglob & 127)];
                float4 wv = *(const float4*)&Wgl[kglob];
                float rn = rinvb[node * HEADS + h];
                float4 v = make_float4(xv.x*wv.x*rn, xv.y*wv.y*rn, xv.z*wv.z*rn, xv.w*wv.w*rn);
                *(uint4*)&Bs[n][c4 * 4] = cvt4(v);
            }
        } else if (BMODE == 1) {
            #pragma unroll
            for (int it = 0; it < 4; it++) {
                int e = tid + it * 128;
                int n = e >> 3, c4 = e & 7;
                float4 v = *(const float4*)&Bb[(long)(colBase + n) * ldb + kb + c4 * 4];
                *(uint4*)&Bs[n][c4 * 4] = cvt4(v);
            }
        } else {
            #pragma unroll
            for (int it = 0; it < 4; it++) {
                int e = tid + it * 128;
                int kk = e & 31, n4 = e >> 5;
                float4 v = *(const float4*)&Bb[(long)(kb + kk) * ldb + colBase + n4 * 4];
                Bs[n4*4 + 0][kk] = f2tf(v.x);
                Bs[n4*4 + 1][kk] = f2tf(v.y);
                Bs[n4*4 + 2][kk] = f2tf(v.z);
                Bs[n4*4 + 3][kk] = f2tf(v.w);
            }
        }
        __syncthreads();

        #pragma unroll
        for (int k8 = 0; k8 < 32; k8 += 8) {
            unsigned af[4][4], bf[4][2];
            #pragma unroll
            for (int i = 0; i < 4; i++) {
                int r = wr + i * 16 + g;
                af[i][0] = As[r    ][k8 + t4];
                af[i][1] = As[r + 8][k8 + t4];
                af[i][2] = As[r    ][k8 + t4 + 4];
                af[i][3] = As[r + 8][k8 + t4 + 4];
            }
            #pragma unroll
            for (int j = 0; j < 4; j++) {
                int n = wc + j * 8 + g;
                bf[j][0] = Bs[n][k8 + t4];
                bf[j][1] = Bs[n][k8 + t4 + 4];
            }
            #pragma unroll
            for (int i = 0; i < 4; i++)
                #pragma unroll
                for (int j = 0; j < 4; j++)
                    mma_tf32(acc[i][j], af[i], bf[j]);
        }
        __syncthreads();
    }

    #pragma unroll
    for (int i = 0; i < 4; i++) {
        int r0 = rowBase + wr + i * 16 + g;
        int r1 = r0 + 8;
        #pragma unroll
        for (int j = 0; j < 4; j++) {
            int c0 = colBase + wc + j * 8 + t4 * 2;
            float v00 = acc[i][j][0], v01 = acc[i][j][1];
            float v10 = acc[i][j][2], v11 = acc[i][j][3];
            if (bias != nullptr) {
                float b0 = bias[c0], b1 = bias[c0 + 1];
                v00 += b0; v01 += b1; v10 += b0; v11 += b1;
            }
            if (EPI == 1) {
                v00 = 1.0f / (1.0f + expf(-v00));
                v01 = 1.0f / (1.0f + expf(-v01));
                v10 = 1.0f / (1.0f + expf(-v10));
                v11 = 1.0f / (1.0f + expf(-v11));
            } else if (EPI == 2) {
                float z00 = Zbuf[(long)r0 * ldz + zoff + c0];
                float z01 = Zbuf[(long)r0 * ldz + zoff + c0 + 1];
                float z10 = Zbuf[(long)r1 * ldz + zoff + c0];
                float z11 = Zbuf[(long)r1 * ldz + zoff + c0 + 1];
                float h00 = Hold[(long)r0 * ldh + c0];
                float h01 = Hold[(long)r0 * ldh + c0 + 1];
                float h10 = Hold[(long)r1 * ldh + c0];
                float h11 = Hold[(long)r1 * ldh + c0 + 1];
                v00 = (1.0f - z00) * h00 + z00 * tanhf(v00);
                v01 = (1.0f - z01) * h01 + z01 * tanhf(v01);
                v10 = (1.0f - z10) * h10 + z10 * tanhf(v10);
                v11 = (1.0f - z11) * h11 + z11 * tanhf(v11);
            }
            *(float2*)&Cb[(long)r0 * ldc + c0] = make_float2(v00, v01);
            *(float2*)&Cb[(long)r1 * ldc + c0] = make_float2(v10, v11);
        }
    }
}

// ---------------- final classifier --------------------------------------------
__global__ __launch_bounds__(256) void fc_kernel(
    const float* __restrict__ h, const float* __restrict__ W,
    const float* __restrict__ bfc, float* __restrict__ out)
{
    int b = blockIdx.x, c = blockIdx.y;
    float s = 0.0f;
    for (int i = threadIdx.x; i < NN * DD; i += 256)
        s += h[(long)b * NN * DD + i] * W[(long)i * NCLS + c];
    #pragma unroll
    for (int o = 16; o; o >>= 1) s += __shfl_xor_sync(0xffffffffu, s, o);
    __shared__ float sh[8];
    if ((threadIdx.x & 31) == 0) sh[threadIdx.x >> 5] = s;
    __syncthreads();
    if (threadIdx.x == 0) {
        float t = 0.0f;
        for (int w = 0; w < 8; w++) t += sh[w];
        out[b * NCLS + c] = t + bfc[c];
    }
}

// ---------------- orchestration -----------------------------------------------
extern "C" void kernel_launch(void* const* d_in, const int* in_sizes, int n_in,
                              void* d_out, int out_size)
{
    const float* x        = (const float*)d_in[0];
    const float* supports = (const float*)d_in[1];
    const float* Wgl      = (const float*)d_in[2];
    const float* Wa       = (const float*)d_in[3];
    const float* ba       = (const float*)d_in[4];
    const float* Wr       = (const float*)d_in[5];
    const float* br       = (const float*)d_in[6];
    const float* Wz       = (const float*)d_in[7];
    const float* bz       = (const float*)d_in[8];
    const float* Wh       = (const float*)d_in[9];
    const float* bh       = (const float*)d_in[10];
    const float* Wfc      = (const float*)d_in[11];
    const float* bfc      = (const float*)d_in[12];
    float* out            = (float*)d_out;

    float *S, *A0, *h0, *h1, *am, *mm, *rz, *ri;
    float *WaT, *WrzT, *WhT, *brz;
    cudaGetSymbolAddress((void**)&S,   g_S);
    cudaGetSymbolAddress((void**)&A0,  g_A0);
    cudaGetSymbolAddress((void**)&h0,  g_h0);
    cudaGetSymbolAddress((void**)&h1,  g_h1);
    cudaGetSymbolAddress((void**)&am,  g_am);
    cudaGetSymbolAddress((void**)&mm,  g_m);
    cudaGetSymbolAddress((void**)&rz,  g_rzb);
    cudaGetSymbolAddress((void**)&ri,  g_ri);
    cudaGetSymbolAddress((void**)&WaT,  g_WaT);
    cudaGetSymbolAddress((void**)&WrzT, g_WrzT);
    cudaGetSymbolAddress((void**)&WhT,  g_WhT);
    cudaGetSymbolAddress((void**)&brz,  g_brz);

    prep_kernel<<<64, 256>>>(Wa, Wr, Wz, Wh, br, bz, WaT, WrzT, WhT, brz);

    // ---- all-timestep attention: rinv, virtual-V NT GEMM over T*B batches ----
    rinv_kernel<<<T_STEPS * BATCH * NN, 128>>>(x, Wgl, ri);
    tgemm<2, 2, 0><<<dim3(NN/64, NN/128, T_STEPS * BATCH), 128>>>(
        nullptr, nullptr, nullptr, 0, KGL,
        nullptr, 0, nullptr, nullptr, 0, 0, nullptr, 0,
        S, NN, KGL, 0, 0, (long)NN * NN, x, Wgl, ri);
    // ---- collapse the A-recurrence to A_15 in one pass ----
    blend_all_kernel<<<BATCH * NN, 256>>>(S, supports, A0);

    // ---- GGNN for the LAST timestep only (only outs[-1] feeds the FC) ----
    const float* xt = x + (long)(T_STEPS - 1) * BATCH * NN * DD;
    const float* hp = xt;
    float* hn = h0;
    for (int s = 0; s < GSTEPS; s++) {
        tgemm<0, 0, 0><<<dim3(2, 2, BATCH), 128>>>(
            A0, nullptr, nullptr, 0, NN,
            hp, DD, nullptr, nullptr, 0, 0, nullptr, 0,
            am, DD, NN, (long)NN * NN, (long)NN * DD, (long)NN * DD,
            nullptr, nullptr, nullptr);
        tgemm<0, 1, 0><<<dim3(2, 64, 1), 128>>>(
            am, nullptr, nullptr, 0, DD,
            WaT, DD, ba, nullptr, 0, 0, nullptr, 0,
            mm, DD, DD, 0, 0, 0, nullptr, nullptr, nullptr);
        tgemm<0, 1, 1><<<dim3(4, 64, 1), 128>>>(
            mm, hp, nullptr, 0, DD,
            WrzT, 2 * DD, brz, nullptr, 0, 0, nullptr, 0,
            rz, 2 * DD, 2 * DD, 0, 0, 0, nullptr, nullptr, nullptr);
        tgemm<0, 1, 2><<<dim3(2, 64, 1), 128>>>(
            mm, hp, rz, 2 * DD, DD,
            WhT, 2 * DD, bh, rz, 2 * DD, DD, hp, DD,
            hn, DD, 2 * DD, 0, 0, 0, nullptr, nullptr, nullptr);
        hp = hn;
        hn = (hn == h0) ? h1 : h0;
    }

    fc_kernel<<<dim3(BATCH, NCLS), 256>>>(hp, Wfc, bfc, out);
    (void)in_sizes; (void)n_in; (void)out_size;
}

// round 4
// speedup vs baseline: 14.9137x; 1.4664x over previous
#include <cuda_runtime.h>
#include <math.h>
#include <stdint.h>

#define T_STEPS 16
#define BATCH   32
#define NN      256
#define DD      128
#define HEADS   16
#define KGL     (HEADS*DD)
#define GSTEPS  5
#define NCLS    2
#define SKIPW   0.3f
#define EPSV    1e-8f

// ---------------- scratch (device globals; no allocation allowed) ------------
__device__ float g_S  [(long)T_STEPS*BATCH*NN*NN];   // weighted-normalized att slices
__device__ float g_A0 [(long)BATCH*NN*NN];           // A_final
__device__ float g_h0 [(long)BATCH*NN*DD];
__device__ float g_h1 [(long)BATCH*NN*DD];
__device__ float g_am [(long)BATCH*NN*DD];
__device__ float g_rzb[(long)BATCH*NN*2*DD];
__device__ float g_ri [(long)T_STEPS*BATCH*NN*HEADS];
__device__ float g_Brz [2*DD*2*DD];   // (N=256, K=256) row-major, Wa folded into top-K
__device__ float g_Bh  [DD*2*DD];     // (N=128, K=256) row-major
__device__ float g_brz2[2*DD];
__device__ float g_bh2 [DD];

// ---------------- tf32 helpers ------------------------------------------------
__device__ __forceinline__ unsigned f2tf(float f) {
    unsigned u;
    asm("cvt.rna.tf32.f32 %0, %1;" : "=r"(u) : "f"(f));
    return u;
}
__device__ __forceinline__ uint4 cvt4(float4 v) {
    uint4 o; o.x = f2tf(v.x); o.y = f2tf(v.y); o.z = f2tf(v.z); o.w = f2tf(v.w);
    return o;
}
__device__ __forceinline__ void mma_tf32(float c[4], const unsigned a[4], const unsigned b[2]) {
    asm volatile(
        "mma.sync.aligned.m16n8k8.row.col.f32.tf32.tf32.f32 "
        "{%0,%1,%2,%3}, {%4,%5,%6,%7}, {%8,%9}, {%0,%1,%2,%3};\n"
        : "+f"(c[0]), "+f"(c[1]), "+f"(c[2]), "+f"(c[3])
        : "r"(a[0]), "r"(a[1]), "r"(a[2]), "r"(a[3]), "r"(b[0]), "r"(b[1]));
}

// ---------------- rinv: 0.25/(||x*w_h|| + eps), warp-parallel over heads -------
__global__ __launch_bounds__(128) void rinv_kernel(
    const float* __restrict__ x, const float* __restrict__ Wgl, float* __restrict__ rinv)
{
    long node = blockIdx.x;          // flat over T*B*N
    int tid = threadIdx.x, lane = tid & 31, w = tid >> 5;
    __shared__ float xs[DD];
    xs[tid] = x[node * DD + tid];
    __syncthreads();
    float4 xv = *(const float4*)&xs[lane * 4];
    #pragma unroll
    for (int hh = 0; hh < 4; hh++) {
        int h = w * 4 + hh;
        float4 wv = *(const float4*)&Wgl[h * DD + lane * 4];
        float a = xv.x * wv.x, b = xv.y * wv.y, c = xv.z * wv.z, d = xv.w * wv.w;
        float ss = a*a + b*b + c*c + d*d;
        #pragma unroll
        for (int o = 16; o; o >>= 1) ss += __shfl_xor_sync(0xffffffffu, ss, o);
        if (lane == 0) rinv[node * HEADS + h] = 0.25f / (sqrtf(ss) + EPSV);
    }
}

// ---------------- fused attention: S_t = w_t * rownorm(relu(V V^T)) ------------
// CTA: 128 rows x 256 cols (full row). 256 threads, 8 warps (2x4), warp 64x64.
// Only B tile (256x32) synthesized; A fragments alias it at rowBase offset.
__global__ __launch_bounds__(256, 1) void att_kernel(
    const float* __restrict__ x, const float* __restrict__ Wgl,
    const float* __restrict__ rinv, float* __restrict__ S)
{
    extern __shared__ __align__(16) unsigned sm[];   // 2 stages x 256 x 36

    const int tid = threadIdx.x;
    const int lane = tid & 31, wid = tid >> 5;
    const int g = lane >> 2, t4 = lane & 3;
    const int wr = (wid >> 2) * 64;
    const int wc = (wid & 3) * 64;
    const int bz = blockIdx.z;                 // t*BATCH + b
    const int rowBase = blockIdx.y * 128;

    const float* xb = x + (long)bz * NN * DD;
    const float* rb = rinv + (long)bz * NN * HEADS;
    float* Sb = S + (long)bz * NN * NN;

    const int myN = tid >> 3;                  // synth: n = myN + it*32
    const int c4  = tid & 7;

    float acc[4][8][4];
    #pragma unroll
    for (int i = 0; i < 4; i++)
        #pragma unroll
        for (int j = 0; j < 8; j++)
            #pragma unroll
            for (int v = 0; v < 4; v++) acc[i][j][v] = 0.0f;

    float4 xs[8]; float rn[8]; float4 ws;

    unsigned* B0 = sm;
    unsigned* B1 = sm + 256 * 36;

    // prologue: stage 0
    {
        int kglob = c4 * 4;
        int h = kglob >> 7, dof = kglob & 127;
        ws = *(const float4*)&Wgl[kglob];
        #pragma unroll
        for (int it = 0; it < 8; it++) {
            int n = myN + it * 32;
            xs[it] = *(const float4*)&xb[(long)n * DD + dof];
            rn[it] = rb[n * HEADS + h];
        }
        #pragma unroll
        for (int it = 0; it < 8; it++) {
            int n = myN + it * 32;
            float r = rn[it];
            float4 v = make_float4(xs[it].x*ws.x*r, xs[it].y*ws.y*r,
                                   xs[it].z*ws.z*r, xs[it].w*ws.w*r);
            *(uint4*)&B0[n * 36 + c4 * 4] = cvt4(v);
        }
    }
    __syncthreads();

    unsigned* cur = B0; unsigned* nxt = B1;
    for (int kbi = 0; kbi < KGL / 32; kbi++) {
        const bool more = (kbi + 1 < KGL / 32);
        if (more) {
            int kglob = (kbi + 1) * 32 + c4 * 4;
            int h = kglob >> 7, dof = kglob & 127;
            ws = *(const float4*)&Wgl[kglob];
            #pragma unroll
            for (int it = 0; it < 8; it++) {
                int n = myN + it * 32;
                xs[it] = *(const float4*)&xb[(long)n * DD + dof];
                rn[it] = rb[n * HEADS + h];
            }
        }
        #pragma unroll
        for (int k8 = 0; k8 < 32; k8 += 8) {
            unsigned af[4][4], bf[8][2];
            #pragma unroll
            for (int i = 0; i < 4; i++) {
                int r = rowBase + wr + i * 16 + g;
                af[i][0] = cur[r * 36 + k8 + t4];
                af[i][1] = cur[(r + 8) * 36 + k8 + t4];
                af[i][2] = cur[r * 36 + k8 + t4 + 4];
                af[i][3] = cur[(r + 8) * 36 + k8 + t4 + 4];
            }
            #pragma unroll
            for (int j = 0; j < 8; j++) {
                int n = wc + j * 8 + g;
                bf[j][0] = cur[n * 36 + k8 + t4];
                bf[j][1] = cur[n * 36 + k8 + t4 + 4];
            }
            #pragma unroll
            for (int i = 0; i < 4; i++)
                #pragma unroll
                for (int j = 0; j < 8; j++)
                    mma_tf32(acc[i][j], af[i], bf[j]);
        }
        if (more) {
            #pragma unroll
            for (int it = 0; it < 8; it++) {
                int n = myN + it * 32;
                float r = rn[it];
                float4 v = make_float4(xs[it].x*ws.x*r, xs[it].y*ws.y*r,
                                       xs[it].z*ws.z*r, xs[it].w*ws.w*r);
                *(uint4*)&nxt[n * 36 + c4 * 4] = cvt4(v);
            }
        }
        __syncthreads();
        unsigned* tmp = cur; cur = nxt; nxt = tmp;
    }

    // ---- epilogue: relu, cross-warp rowsum, normalize, weight, store ----
    float* rsm = (float*)sm;                   // [128][5]
    int t = bz >> 5;
    float wt = 0.7f * powf(SKIPW, (float)(T_STEPS - 1 - t));

    #pragma unroll
    for (int i = 0; i < 4; i++)
        #pragma unroll
        for (int j = 0; j < 8; j++)
            #pragma unroll
            for (int v = 0; v < 4; v++) acc[i][j][v] = fmaxf(acc[i][j][v], 0.0f);

    #pragma unroll
    for (int i = 0; i < 4; i++) {
        float s0 = 0.0f, s1 = 0.0f;
        #pragma unroll
        for (int j = 0; j < 8; j++) {
            s0 += acc[i][j][0] + acc[i][j][1];
            s1 += acc[i][j][2] + acc[i][j][3];
        }
        s0 += __shfl_xor_sync(0xffffffffu, s0, 1);
        s0 += __shfl_xor_sync(0xffffffffu, s0, 2);
        s1 += __shfl_xor_sync(0xffffffffu, s1, 1);
        s1 += __shfl_xor_sync(0xffffffffu, s1, 2);
        if (t4 == 0) {
            rsm[(wr + i * 16 + g) * 5 + (wid & 3)] = s0;
            rsm[(wr + i * 16 + g + 8) * 5 + (wid & 3)] = s1;
        }
    }
    __syncthreads();
    #pragma unroll
    for (int i = 0; i < 4; i++) {
        int r0 = wr + i * 16 + g, r1 = r0 + 8;
        float tot0 = rsm[r0*5+0] + rsm[r0*5+1] + rsm[r0*5+2] + rsm[r0*5+3];
        float tot1 = rsm[r1*5+0] + rsm[r1*5+1] + rsm[r1*5+2] + rsm[r1*5+3];
        float inv0 = wt / (tot0 + EPSV);
        float inv1 = wt / (tot1 + EPSV);
        #pragma unroll
        for (int j = 0; j < 8; j++) {
            int c0 = wc + j * 8 + t4 * 2;
            *(float2*)&Sb[(long)(rowBase + r0) * NN + c0] =
                make_float2(acc[i][j][0] * inv0, acc[i][j][1] * inv0);
            *(float2*)&Sb[(long)(rowBase + r1) * NN + c0] =
                make_float2(acc[i][j][2] * inv1, acc[i][j][3] * inv1);
        }
    }
}

// ---------------- A = 0.3^16 * supports + sum_t S_t ---------------------------
__global__ __launch_bounds__(256) void reduce_kernel(
    const float* __restrict__ S, const float* __restrict__ sup, float* __restrict__ A)
{
    long i4 = (long)blockIdx.x * 256 + threadIdx.x;   // over B*N*N/4 float4s
    const float4* S4 = (const float4*)S;
    const float4* P4 = (const float4*)sup;
    float4* A4 = (float4*)A;
    int b = (int)(i4 >> 14);
    long rem = i4 & 16383;
    const float k16 = 4.3046721e-8f;                  // 0.3^16
    float4 p = P4[i4];
    float4 a = make_float4(p.x * k16, p.y * k16, p.z * k16, p.w * k16);
    #pragma unroll
    for (int t = 0; t < T_STEPS; t++) {
        float4 v = S4[(((long)(t * BATCH + b)) << 14) + rem];
        a.x += v.x; a.y += v.y; a.z += v.z; a.w += v.w;
    }
    A4[i4] = a;
}

// ------- prep: fold Wa/ba into gate weights; build (N,K) row-major blocks ------
__global__ void prep_kernel(
    const float* __restrict__ Wa, const float* __restrict__ Wr,
    const float* __restrict__ Wz, const float* __restrict__ Wh,
    const float* __restrict__ ba, const float* __restrict__ br,
    const float* __restrict__ bz, const float* __restrict__ bh,
    float* __restrict__ Brz, float* __restrict__ Bh_,
    float* __restrict__ brz2, float* __restrict__ bh2)
{
    int idx = blockIdx.x * blockDim.x + threadIdx.x;
    if (idx < 65536) {
        int n = idx >> 8, k = idx & 255, np = n & 127;
        const float* W = (n < 128) ? Wr : Wz;
        float v;
        if (k < 128) {
            v = 0.0f;
            for (int d = 0; d < 128; d++) v += Wa[k * 128 + d] * W[d * 128 + np];
        } else v = W[k * 128 + np];
        Brz[n * 256 + k] = v;
    } else if (idx < 98304) {
        int e = idx - 65536, n = e >> 8, k = e & 255;
        float v;
        if (k < 128) {
            v = 0.0f;
            for (int d = 0; d < 128; d++) v += Wa[k * 128 + d] * Wh[d * 128 + n];
        } else v = Wh[k * 128 + n];
        Bh_[n * 256 + k] = v;
    } else if (idx < 98560) {
        int n = idx - 98304, np = n & 127;
        const float* W = (n < 128) ? Wr : Wz;
        float v = (n < 128) ? br[np] : bz[np];
        for (int d = 0; d < 128; d++) v += ba[d] * W[d * 128 + np];
        brz2[n] = v;
    } else if (idx < 98688) {
        int n = idx - 98560;
        float v = bh[n];
        for (int d = 0; d < 128; d++) v += ba[d] * Wh[d * 128 + n];
        bh2[n] = v;
    }
}

// ---------------- tf32 tensor-core GEMM (GGNN) --------------------------------
template<int BMODE, int EPI>
__global__ __launch_bounds__(128) void tgemm(
    const float* __restrict__ A1, const float* __restrict__ A2,
    const float* __restrict__ A2m, int ldm, int K1,
    const float* __restrict__ Bmat, int ldb,
    const float* __restrict__ bias,
    const float* __restrict__ Zbuf, int ldz, int zoff,
    const float* __restrict__ Hold, int ldh,
    float* __restrict__ C, int ldc,
    int K, long sA, long sB, long sC)
{
    __shared__ __align__(16) unsigned As[128][36];
    __shared__ __align__(16) unsigned Bs[64][36];

    const int tid = threadIdx.x;
    const int lane = tid & 31, wid = tid >> 5;
    const int wr = (wid >> 1) * 64;
    const int wc = (wid & 1) * 32;
    const int g = lane >> 2, t4 = lane & 3;

    const int bz_ = blockIdx.z;
    const int rowBase = blockIdx.y * 128;
    const int colBase = blockIdx.x * 64;

    const float* A1b = A1 + (long)bz_ * sA;
    const float* Bb  = Bmat + (long)bz_ * sB;
    float*       Cb  = C + (long)bz_ * sC;

    float acc[4][4][4] = {};

    for (int kb = 0; kb < K; kb += 32) {
        const float* Asrc; int lda_, kofs; bool mult;
        if (kb < K1) { Asrc = A1b; lda_ = K1;     kofs = kb;       mult = false; }
        else         { Asrc = A2;  lda_ = K - K1; kofs = kb - K1;  mult = (A2m != nullptr); }
        #pragma unroll
        for (int it = 0; it < 8; it++) {
            int e = tid + it * 128;
            int r = e >> 3, c4 = e & 7;
            float4 v = *(const float4*)&Asrc[(long)(rowBase + r) * lda_ + kofs + c4 * 4];
            if (mult) {
                float4 mv = *(const float4*)&A2m[(long)(rowBase + r) * ldm + kofs + c4 * 4];
                v.x *= mv.x; v.y *= mv.y; v.z *= mv.z; v.w *= mv.w;
            }
            *(uint4*)&As[r][c4 * 4] = cvt4(v);
        }
        if (BMODE == 1) {
            #pragma unroll
            for (int it = 0; it < 4; it++) {
                int e = tid + it * 128;
                int n = e >> 3, c4 = e & 7;
                float4 v = *(const float4*)&Bb[(long)(colBase + n) * ldb + kb + c4 * 4];
                *(uint4*)&Bs[n][c4 * 4] = cvt4(v);
            }
        } else {
            #pragma unroll
            for (int it = 0; it < 4; it++) {
                int e = tid + it * 128;
                int kk = e & 31, n4 = e >> 5;
                float4 v = *(const float4*)&Bb[(long)(kb + kk) * ldb + colBase + n4 * 4];
                Bs[n4*4 + 0][kk] = f2tf(v.x);
                Bs[n4*4 + 1][kk] = f2tf(v.y);
                Bs[n4*4 + 2][kk] = f2tf(v.z);
                Bs[n4*4 + 3][kk] = f2tf(v.w);
            }
        }
        __syncthreads();

        #pragma unroll
        for (int k8 = 0; k8 < 32; k8 += 8) {
            unsigned af[4][4], bf[4][2];
            #pragma unroll
            for (int i = 0; i < 4; i++) {
                int r = wr + i * 16 + g;
                af[i][0] = As[r    ][k8 + t4];
                af[i][1] = As[r + 8][k8 + t4];
                af[i][2] = As[r    ][k8 + t4 + 4];
                af[i][3] = As[r + 8][k8 + t4 + 4];
            }
            #pragma unroll
            for (int j = 0; j < 4; j++) {
                int n = wc + j * 8 + g;
                bf[j][0] = Bs[n][k8 + t4];
                bf[j][1] = Bs[n][k8 + t4 + 4];
            }
            #pragma unroll
            for (int i = 0; i < 4; i++)
                #pragma unroll
                for (int j = 0; j < 4; j++)
                    mma_tf32(acc[i][j], af[i], bf[j]);
        }
        __syncthreads();
    }

    #pragma unroll
    for (int i = 0; i < 4; i++) {
        int r0 = rowBase + wr + i * 16 + g;
        int r1 = r0 + 8;
        #pragma unroll
        for (int j = 0; j < 4; j++) {
            int c0 = colBase + wc + j * 8 + t4 * 2;
            float v00 = acc[i][j][0], v01 = acc[i][j][1];
            float v10 = acc[i][j][2], v11 = acc[i][j][3];
            if (bias != nullptr) {
                float b0 = bias[c0], b1 = bias[c0 + 1];
                v00 += b0; v01 += b1; v10 += b0; v11 += b1;
            }
            if (EPI == 1) {
                v00 = 1.0f / (1.0f + expf(-v00));
                v01 = 1.0f / (1.0f + expf(-v01));
                v10 = 1.0f / (1.0f + expf(-v10));
                v11 = 1.0f / (1.0f + expf(-v11));
            } else if (EPI == 2) {
                float z00 = Zbuf[(long)r0 * ldz + zoff + c0];
                float z01 = Zbuf[(long)r0 * ldz + zoff + c0 + 1];
                float z10 = Zbuf[(long)r1 * ldz + zoff + c0];
                float z11 = Zbuf[(long)r1 * ldz + zoff + c0 + 1];
                float h00 = Hold[(long)r0 * ldh + c0];
                float h01 = Hold[(long)r0 * ldh + c0 + 1];
                float h10 = Hold[(long)r1 * ldh + c0];
                float h11 = Hold[(long)r1 * ldh + c0 + 1];
                v00 = (1.0f - z00) * h00 + z00 * tanhf(v00);
                v01 = (1.0f - z01) * h01 + z01 * tanhf(v01);
                v10 = (1.0f - z10) * h10 + z10 * tanhf(v10);
                v11 = (1.0f - z11) * h11 + z11 * tanhf(v11);
            }
            *(float2*)&Cb[(long)r0 * ldc + c0] = make_float2(v00, v01);
            *(float2*)&Cb[(long)r1 * ldc + c0] = make_float2(v10, v11);
        }
    }
}

// ---------------- final classifier --------------------------------------------
__global__ __launch_bounds__(256) void fc_kernel(
    const float* __restrict__ h, const float* __restrict__ W,
    const float* __restrict__ bfc, float* __restrict__ out)
{
    int b = blockIdx.x, c = blockIdx.y;
    float s = 0.0f;
    for (int i = threadIdx.x; i < NN * DD; i += 256)
        s += h[(long)b * NN * DD + i] * W[(long)i * NCLS + c];
    #pragma unroll
    for (int o = 16; o; o >>= 1) s += __shfl_xor_sync(0xffffffffu, s, o);
    __shared__ float sh[8];
    if ((threadIdx.x & 31) == 0) sh[threadIdx.x >> 5] = s;
    __syncthreads();
    if (threadIdx.x == 0) {
        float t = 0.0f;
        for (int w = 0; w < 8; w++) t += sh[w];
        out[b * NCLS + c] = t + bfc[c];
    }
}

// ---------------- orchestration -----------------------------------------------
extern "C" void kernel_launch(void* const* d_in, const int* in_sizes, int n_in,
                              void* d_out, int out_size)
{
    const float* x        = (const float*)d_in[0];
    const float* supports = (const float*)d_in[1];
    const float* Wgl      = (const float*)d_in[2];
    const float* Wa       = (const float*)d_in[3];
    const float* ba       = (const float*)d_in[4];
    const float* Wr       = (const float*)d_in[5];
    const float* br       = (const float*)d_in[6];
    const float* Wz       = (const float*)d_in[7];
    const float* bz       = (const float*)d_in[8];
    const float* Wh       = (const float*)d_in[9];
    const float* bh       = (const float*)d_in[10];
    const float* Wfc      = (const float*)d_in[11];
    const float* bfc      = (const float*)d_in[12];
    float* out            = (float*)d_out;

    float *S, *A0, *h0, *h1, *am, *rz, *ri, *Brz, *Bh_, *brz2, *bh2;
    cudaGetSymbolAddress((void**)&S,    g_S);
    cudaGetSymbolAddress((void**)&A0,   g_A0);
    cudaGetSymbolAddress((void**)&h0,   g_h0);
    cudaGetSymbolAddress((void**)&h1,   g_h1);
    cudaGetSymbolAddress((void**)&am,   g_am);
    cudaGetSymbolAddress((void**)&rz,   g_rzb);
    cudaGetSymbolAddress((void**)&ri,   g_ri);
    cudaGetSymbolAddress((void**)&Brz,  g_Brz);
    cudaGetSymbolAddress((void**)&Bh_,  g_Bh);
    cudaGetSymbolAddress((void**)&brz2, g_brz2);
    cudaGetSymbolAddress((void**)&bh2,  g_bh2);

    static bool attr_set = false;
    if (!attr_set) {
        cudaFuncSetAttribute(att_kernel, cudaFuncAttributeMaxDynamicSharedMemorySize,
                             2 * 256 * 36 * 4);
        attr_set = true;
    }

    prep_kernel<<<386, 256>>>(Wa, Wr, Wz, Wh, ba, br, bz, bh, Brz, Bh_, brz2, bh2);

    // ---- attention for all timesteps, fused normalize+weight ----
    rinv_kernel<<<T_STEPS * BATCH * NN, 128>>>(x, Wgl, ri);
    att_kernel<<<dim3(1, 2, T_STEPS * BATCH), 256, 2 * 256 * 36 * 4>>>(x, Wgl, ri, S);
    reduce_kernel<<<(BATCH * NN * NN / 4) / 256, 256>>>(S, supports, A0);

    // ---- GGNN for last timestep only (Wa folded into gate weights) ----
    const float* xt = x + (long)(T_STEPS - 1) * BATCH * NN * DD;
    const float* hp = xt;
    float* hn = h0;
    for (int s = 0; s < GSTEPS; s++) {
        // am = A @ h   (batched, BMODE=0: B=(K,N) row-major)
        tgemm<0, 0><<<dim3(2, 2, BATCH), 128>>>(
            A0, nullptr, nullptr, 0, NN,
            hp, DD, nullptr, nullptr, 0, 0, nullptr, 0,
            am, DD, NN, (long)NN * NN, (long)NN * DD, (long)NN * DD);
        // [r|z] = sigmoid([am|h] @ Brz + brz2)
        tgemm<1, 1><<<dim3(4, 64, 1), 128>>>(
            am, hp, nullptr, 0, DD,
            Brz, 2 * DD, brz2, nullptr, 0, 0, nullptr, 0,
            rz, 2 * DD, 2 * DD, 0, 0, 0);
        // h' = (1-z)h + z*tanh([am | r*h] @ Bh + bh2)
        tgemm<1, 2><<<dim3(2, 64, 1), 128>>>(
            am, hp, rz, 2 * DD, DD,
            Bh_, 2 * DD, bh2, rz, 2 * DD, DD, hp, DD,
            hn, DD, 2 * DD, 0, 0, 0);
        hp = hn;
        hn = (hn == h0) ? h1 : h0;
    }

    fc_kernel<<<dim3(BATCH, NCLS), 256>>>(hp, Wfc, bfc, out);
    (void)in_sizes; (void)n_in; (void)out_size;
}

// round 6
// speedup vs baseline: 20.5917x; 1.3807x over previous
#include <cuda_runtime.h>
#include <cuda_fp16.h>
#include <math.h>
#include <stdint.h>

#define T_STEPS 16
#define BATCH   32
#define NN      256
#define DD      128
#define HEADS   16
#define KGL     (HEADS*DD)
#define GSTEPS  5
#define NCLS    2
#define SKIPW   0.3f
#define EPSV    1e-8f

// ---------------- scratch (device globals; no allocation allowed) ------------
__device__ float g_S  [(long)T_STEPS*BATCH*NN*NN];   // weighted-normalized att slices
__device__ float g_A0 [(long)BATCH*NN*NN];           // A_final
__device__ float g_h0 [(long)BATCH*NN*DD];
__device__ float g_h1 [(long)BATCH*NN*DD];
__device__ float g_hT0[(long)BATCH*NN*DD];
__device__ float g_hT1[(long)BATCH*NN*DD];
__device__ float g_xT [(long)BATCH*NN*DD];
__device__ float g_ri [(long)T_STEPS*BATCH*NN*HEADS];
__device__ __half g_Brz_h[2*DD*2*DD];   // (N=256,K=256) row-major, Wa folded into k<128
__device__ __half g_Bh_h [DD*2*DD];     // (N=128,K=256) row-major
__device__ float  g_brz2[2*DD];
__device__ float  g_bh2 [DD];

// ---------------- fp16 helpers -------------------------------------------------
__device__ __forceinline__ unsigned pk2(float a, float b) {
    __half2 h = __floats2half2_rn(a, b);
    return *(unsigned*)&h;
}
__device__ __forceinline__ uint2 pk4(float4 v) {
    return make_uint2(pk2(v.x, v.y), pk2(v.z, v.w));
}
__device__ __forceinline__ unsigned hmul2u(unsigned a, unsigned b) {
    __half2 r = __hmul2(*(__half2*)&a, *(__half2*)&b);
    return *(unsigned*)&r;
}
__device__ __forceinline__ void mma_f16(float c[4], const unsigned a[4], const unsigned b[2]) {
    asm volatile(
        "mma.sync.aligned.m16n8k16.row.col.f32.f16.f16.f32 "
        "{%0,%1,%2,%3}, {%4,%5,%6,%7}, {%8,%9}, {%0,%1,%2,%3};\n"
        : "+f"(c[0]), "+f"(c[1]), "+f"(c[2]), "+f"(c[3])
        : "r"(a[0]), "r"(a[1]), "r"(a[2]), "r"(a[3]), "r"(b[0]), "r"(b[1]));
}

// ---------------- rinv: 0.25/(||x*w_h|| + eps) ---------------------------------
__global__ __launch_bounds__(128) void rinv_kernel(
    const float* __restrict__ x, const float* __restrict__ Wgl, float* __restrict__ rinv)
{
    long node = blockIdx.x;
    int tid = threadIdx.x, lane = tid & 31, w = tid >> 5;
    __shared__ float xs[DD];
    xs[tid] = x[node * DD + tid];
    __syncthreads();
    float4 xv = *(const float4*)&xs[lane * 4];
    #pragma unroll
    for (int hh = 0; hh < 4; hh++) {
        int h = w * 4 + hh;
        float4 wv = *(const float4*)&Wgl[h * DD + lane * 4];
        float a = xv.x * wv.x, b = xv.y * wv.y, c = xv.z * wv.z, d = xv.w * wv.w;
        float ss = a*a + b*b + c*c + d*d;
        #pragma unroll
        for (int o = 16; o; o >>= 1) ss += __shfl_xor_sync(0xffffffffu, ss, o);
        if (lane == 0) rinv[node * HEADS + h] = 0.25f / (sqrtf(ss) + EPSV);
    }
}

// ---------------- fused attention (fp16 MMA): S_t = w_t*rownorm(relu(VV^T)) ----
__global__ __launch_bounds__(256, 1) void att_kernel(
    const float* __restrict__ x, const float* __restrict__ Wgl,
    const float* __restrict__ rinv, float* __restrict__ S)
{
    extern __shared__ __align__(16) unsigned smA[];   // 2 stages x 256 x 20 uints

    const int tid = threadIdx.x;
    const int lane = tid & 31, wid = tid >> 5;
    const int g = lane >> 2, t4 = lane & 3;
    const int wr = (wid >> 2) * 64;
    const int wc = (wid & 3) * 64;
    const int bz = blockIdx.z;
    const int rowBase = blockIdx.y * 128;

    const float* xb = x + (long)bz * NN * DD;
    const float* rb = rinv + (long)bz * NN * HEADS;
    float* Sb = S + (long)bz * NN * NN;

    const int myN = tid >> 3;
    const int c4  = tid & 7;

    float acc[4][8][4] = {};
    float4 xs[8]; float rn[8]; float4 ws;

    unsigned* B0 = smA;
    unsigned* B1 = smA + 256 * 20;

    {
        int kglob = c4 * 4;
        int h = kglob >> 7, dof = kglob & 127;
        ws = *(const float4*)&Wgl[kglob];
        #pragma unroll
        for (int it = 0; it < 8; it++) {
            int n = myN + it * 32;
            xs[it] = *(const float4*)&xb[(long)n * DD + dof];
            rn[it] = rb[n * HEADS + h];
        }
        #pragma unroll
        for (int it = 0; it < 8; it++) {
            int n = myN + it * 32;
            float r = rn[it];
            float4 v = make_float4(xs[it].x*ws.x*r, xs[it].y*ws.y*r,
                                   xs[it].z*ws.z*r, xs[it].w*ws.w*r);
            *(uint2*)&B0[n * 20 + c4 * 2] = pk4(v);
        }
    }
    __syncthreads();

    unsigned* cur = B0; unsigned* nxt = B1;
    for (int kbi = 0; kbi < KGL / 32; kbi++) {
        const bool more = (kbi + 1 < KGL / 32);
        if (more) {
            int kglob = (kbi + 1) * 32 + c4 * 4;
            int h = kglob >> 7, dof = kglob & 127;
            ws = *(const float4*)&Wgl[kglob];
            #pragma unroll
            for (int it = 0; it < 8; it++) {
                int n = myN + it * 32;
                xs[it] = *(const float4*)&xb[(long)n * DD + dof];
                rn[it] = rb[n * HEADS + h];
            }
        }
        #pragma unroll
        for (int k8 = 0; k8 < 2; k8++) {
            unsigned af[4][4], bf[8][2];
            #pragma unroll
            for (int i = 0; i < 4; i++) {
                int r = rowBase + wr + i * 16 + g;
                af[i][0] = cur[r * 20 + k8 * 8 + t4];
                af[i][1] = cur[(r + 8) * 20 + k8 * 8 + t4];
                af[i][2] = cur[r * 20 + k8 * 8 + t4 + 4];
                af[i][3] = cur[(r + 8) * 20 + k8 * 8 + t4 + 4];
            }
            #pragma unroll
            for (int j = 0; j < 8; j++) {
                int n = wc + j * 8 + g;
                bf[j][0] = cur[n * 20 + k8 * 8 + t4];
                bf[j][1] = cur[n * 20 + k8 * 8 + t4 + 4];
            }
            #pragma unroll
            for (int i = 0; i < 4; i++)
                #pragma unroll
                for (int j = 0; j < 8; j++)
                    mma_f16(acc[i][j], af[i], bf[j]);
        }
        if (more) {
            #pragma unroll
            for (int it = 0; it < 8; it++) {
                int n = myN + it * 32;
                float r = rn[it];
                float4 v = make_float4(xs[it].x*ws.x*r, xs[it].y*ws.y*r,
                                       xs[it].z*ws.z*r, xs[it].w*ws.w*r);
                *(uint2*)&nxt[n * 20 + c4 * 2] = pk4(v);
            }
        }
        __syncthreads();
        unsigned* tmp = cur; cur = nxt; nxt = tmp;
    }

    // ---- epilogue: relu, cross-warp rowsum, normalize, weight, store ----
    float* rsm = (float*)smA;                  // [128][5]
    int t = bz >> 5;
    float wt = 0.7f * powf(SKIPW, (float)(T_STEPS - 1 - t));

    #pragma unroll
    for (int i = 0; i < 4; i++)
        #pragma unroll
        for (int j = 0; j < 8; j++)
            #pragma unroll
            for (int v = 0; v < 4; v++) acc[i][j][v] = fmaxf(acc[i][j][v], 0.0f);

    #pragma unroll
    for (int i = 0; i < 4; i++) {
        float s0 = 0.0f, s1 = 0.0f;
        #pragma unroll
        for (int j = 0; j < 8; j++) {
            s0 += acc[i][j][0] + acc[i][j][1];
            s1 += acc[i][j][2] + acc[i][j][3];
        }
        s0 += __shfl_xor_sync(0xffffffffu, s0, 1);
        s0 += __shfl_xor_sync(0xffffffffu, s0, 2);
        s1 += __shfl_xor_sync(0xffffffffu, s1, 1);
        s1 += __shfl_xor_sync(0xffffffffu, s1, 2);
        if (t4 == 0) {
            rsm[(wr + i * 16 + g) * 5 + (wid & 3)] = s0;
            rsm[(wr + i * 16 + g + 8) * 5 + (wid & 3)] = s1;
        }
    }
    __syncthreads();
    #pragma unroll
    for (int i = 0; i < 4; i++) {
        int r0 = wr + i * 16 + g, r1 = r0 + 8;
        float tot0 = rsm[r0*5+0] + rsm[r0*5+1] + rsm[r0*5+2] + rsm[r0*5+3];
        float tot1 = rsm[r1*5+0] + rsm[r1*5+1] + rsm[r1*5+2] + rsm[r1*5+3];
        float inv0 = wt / (tot0 + EPSV);
        float inv1 = wt / (tot1 + EPSV);
        #pragma unroll
        for (int j = 0; j < 8; j++) {
            int c0 = wc + j * 8 + t4 * 2;
            *(float2*)&Sb[(long)(rowBase + r0) * NN + c0] =
                make_float2(acc[i][j][0] * inv0, acc[i][j][1] * inv0);
            *(float2*)&Sb[(long)(rowBase + r1) * NN + c0] =
                make_float2(acc[i][j][2] * inv1, acc[i][j][3] * inv1);
        }
    }
}

// ---------------- A = 0.3^16 * supports + sum_t S_t ---------------------------
__global__ __launch_bounds__(256) void reduce_kernel(
    const float* __restrict__ S, const float* __restrict__ sup, float* __restrict__ A)
{
    long i4 = (long)blockIdx.x * 256 + threadIdx.x;
    const float4* S4 = (const float4*)S;
    const float4* P4 = (const float4*)sup;
    float4* A4 = (float4*)A;
    int b = (int)(i4 >> 14);
    long rem = i4 & 16383;
    const float k16 = 4.3046721e-8f;
    float4 p = P4[i4];
    float4 a = make_float4(p.x * k16, p.y * k16, p.z * k16, p.w * k16);
    #pragma unroll
    for (int t = 0; t < T_STEPS; t++) {
        float4 v = S4[(((long)(t * BATCH + b)) << 14) + rem];
        a.x += v.x; a.y += v.y; a.z += v.z; a.w += v.w;
    }
    A4[i4] = a;
}

// ------- prep: fold Wa/ba into gate weights; output fp16 (N,K) blocks ----------
// Gate weights are (2D,128): rows 0..127 = a-block, rows 128..255 = h-block.
// For k>=128 we must read row k (h-block), NOT row k-128.
__global__ void prep_kernel(
    const float* __restrict__ Wa, const float* __restrict__ Wr,
    const float* __restrict__ Wz, const float* __restrict__ Wh,
    const float* __restrict__ ba, const float* __restrict__ br,
    const float* __restrict__ bz, const float* __restrict__ bh,
    __half* __restrict__ Brz, __half* __restrict__ Bh_,
    float* __restrict__ brz2, float* __restrict__ bh2)
{
    int idx = blockIdx.x * blockDim.x + threadIdx.x;
    if (idx < 65536) {
        int n = idx >> 8, k = idx & 255, np = n & 127;
        const float* W = (n < 128) ? Wr : Wz;
        float v;
        if (k < 128) {
            v = 0.0f;
            for (int d = 0; d < 128; d++) v += Wa[k * 128 + d] * W[d * 128 + np];
        } else v = W[k * 128 + np];
        Brz[n * 256 + k] = __float2half(v);
    } else if (idx < 98304) {
        int e = idx - 65536, n = e >> 8, k = e & 255;
        float v;
        if (k < 128) {
            v = 0.0f;
            for (int d = 0; d < 128; d++) v += Wa[k * 128 + d] * Wh[d * 128 + n];
        } else v = Wh[k * 128 + n];
        Bh_[n * 256 + k] = __float2half(v);
    } else if (idx < 98560) {
        int n = idx - 98304, np = n & 127;
        const float* W = (n < 128) ? Wr : Wz;
        float v = (n < 128) ? br[np] : bz[np];
        for (int d = 0; d < 128; d++) v += ba[d] * W[d * 128 + np];
        brz2[n] = v;
    } else if (idx < 98688) {
        int n = idx - 98560;
        float v = bh[n];
        for (int d = 0; d < 128; d++) v += ba[d] * Wh[d * 128 + n];
        bh2[n] = v;
    }
}

// ---------------- per-batch (N,D) -> (D,N) transpose ---------------------------
__global__ void transpose_k(const float* __restrict__ src, float* __restrict__ dst)
{
    __shared__ float tile[32][33];
    int b = blockIdx.z;
    int n0 = blockIdx.x * 32, d0 = blockIdx.y * 32;
    const float* s = src + (long)b * NN * DD;
    float* o = dst + (long)b * NN * DD;
    #pragma unroll
    for (int k = 0; k < 4; k++)
        tile[threadIdx.y + k * 8][threadIdx.x] =
            s[(long)(n0 + threadIdx.y + k * 8) * DD + d0 + threadIdx.x];
    __syncthreads();
    #pragma unroll
    for (int k = 0; k < 4; k++)
        o[(long)(d0 + threadIdx.y + k * 8) * NN + n0 + threadIdx.x] =
            tile[threadIdx.x][threadIdx.y + k * 8];
}

// ---------------- fully fused GGNN step ---------------------------------------
__global__ __launch_bounds__(128) void ggnn_step(
    const float* __restrict__ A, const float* __restrict__ h_in,
    const float* __restrict__ hT_in,
    const __half* __restrict__ Brz, const float* __restrict__ brz,
    const __half* __restrict__ Bh, const float* __restrict__ bh,
    float* __restrict__ h_out, float* __restrict__ hT_out)
{
    extern __shared__ __align__(16) unsigned smG[];
    unsigned* sAm = smG;                  // [64][68]  am fp16 pairs
    unsigned* sH  = sAm + 64 * 68;        // [64][68]  own h rows fp16
    unsigned* sRZ = sH  + 64 * 68;        // [64][132] r pairs 0..63, z pairs 64..127
    unsigned* sB  = sRZ + 64 * 132;       // stream buffer (max [256][20])
    unsigned* sA1 = sB  + 256 * 20;       // [64][20]  adjacency chunk fp16

    const int tid = threadIdx.x, lane = tid & 31, wid = tid >> 5;
    const int g = lane >> 2, t4 = lane & 3;
    const int b = blockIdx.y, r0 = blockIdx.x * 64;
    const int wr = (wid >> 1) * 32;
    const int wcn = (wid & 1) * 64;

    const float* Ab  = A + (long)b * NN * NN;
    const float* hb  = h_in + (long)b * NN * DD;
    const float* hTb = hT_in + (long)b * NN * DD;
    float* hob  = h_out + (long)b * NN * DD;
    float* hTob = hT_out + (long)b * NN * DD;

    #pragma unroll
    for (int i = 0; i < 16; i++) {
        int e = tid + i * 128;
        int r = e >> 5, c4 = e & 31;
        float4 v = *(const float4*)&hb[(long)(r0 + r) * DD + c4 * 4];
        *(uint2*)&sH[r * 68 + c4 * 2] = pk4(v);
    }

    // ================= Phase 1: am = A @ h =================
    float acc1[2][8][4] = {};
    for (int kb = 0; kb < 256; kb += 32) {
        #pragma unroll
        for (int i = 0; i < 4; i++) {
            int e = tid + i * 128;
            int r = e >> 3, c4 = e & 7;
            float4 v = *(const float4*)&Ab[(long)(r0 + r) * NN + kb + c4 * 4];
            *(uint2*)&sA1[r * 20 + c4 * 2] = pk4(v);
        }
        #pragma unroll
        for (int i = 0; i < 8; i++) {
            int e = tid + i * 128;
            int d = e >> 3, nq = e & 7;
            float4 v = *(const float4*)&hTb[(long)d * NN + kb + nq * 4];
            *(uint2*)&sB[d * 18 + nq * 2] = pk4(v);
        }
        __syncthreads();
        #pragma unroll
        for (int k8 = 0; k8 < 2; k8++) {
            unsigned af[2][4], bf[8][2];
            #pragma unroll
            for (int i = 0; i < 2; i++) {
                int row = wr + i * 16 + g;
                af[i][0] = sA1[row * 20 + k8 * 8 + t4];
                af[i][1] = sA1[(row + 8) * 20 + k8 * 8 + t4];
                af[i][2] = sA1[row * 20 + k8 * 8 + t4 + 4];
                af[i][3] = sA1[(row + 8) * 20 + k8 * 8 + t4 + 4];
            }
            #pragma unroll
            for (int j = 0; j < 8; j++) {
                int n = wcn + j * 8 + g;
                bf[j][0] = sB[n * 18 + k8 * 8 + t4];
                bf[j][1] = sB[n * 18 + k8 * 8 + t4 + 4];
            }
            #pragma unroll
            for (int i = 0; i < 2; i++)
                #pragma unroll
                for (int j = 0; j < 8; j++)
                    mma_f16(acc1[i][j], af[i], bf[j]);
        }
        __syncthreads();
    }
    #pragma unroll
    for (int i = 0; i < 2; i++) {
        int row = wr + i * 16 + g;
        #pragma unroll
        for (int j = 0; j < 8; j++) {
            int colp = ((wcn + j * 8) >> 1) + t4;
            sAm[row * 68 + colp]       = pk2(acc1[i][j][0], acc1[i][j][1]);
            sAm[(row + 8) * 68 + colp] = pk2(acc1[i][j][2], acc1[i][j][3]);
        }
    }
    __syncthreads();

    // ================= Phase 2: [r|z] = sigmoid([am|h] @ Brz + brz2) ==========
    {
        const int wc2 = (wid & 1) * 128;
        float acc2[2][16][4] = {};
        for (int kb = 0; kb < 256; kb += 32) {
            #pragma unroll
            for (int i = 0; i < 8; i++) {
                int e = tid + i * 128;
                int n = e >> 2, c8 = e & 3;
                uint4 v = *(const uint4*)(Brz + (long)n * 256 + kb + c8 * 8);
                *(uint4*)&sB[n * 20 + c8 * 4] = v;
            }
            __syncthreads();
            const unsigned* src = (kb < 128) ? sAm : sH;
            #pragma unroll
            for (int k8 = 0; k8 < 2; k8++) {
                int pb = ((kb & 127) >> 1) + k8 * 8;
                unsigned af[2][4], bf[16][2];
                #pragma unroll
                for (int i = 0; i < 2; i++) {
                    int row = wr + i * 16 + g;
                    af[i][0] = src[row * 68 + pb + t4];
                    af[i][1] = src[(row + 8) * 68 + pb + t4];
                    af[i][2] = src[row * 68 + pb + t4 + 4];
                    af[i][3] = src[(row + 8) * 68 + pb + t4 + 4];
                }
                #pragma unroll
                for (int j = 0; j < 16; j++) {
                    int n = wc2 + j * 8 + g;
                    bf[j][0] = sB[n * 20 + k8 * 8 + t4];
                    bf[j][1] = sB[n * 20 + k8 * 8 + t4 + 4];
                }
                #pragma unroll
                for (int i = 0; i < 2; i++)
                    #pragma unroll
                    for (int j = 0; j < 16; j++)
                        mma_f16(acc2[i][j], af[i], bf[j]);
            }
            __syncthreads();
        }
        #pragma unroll
        for (int i = 0; i < 2; i++) {
            int row = wr + i * 16 + g;
            #pragma unroll
            for (int j = 0; j < 16; j++) {
                int col = wc2 + j * 8 + 2 * t4;
                float b0 = brz[col], b1 = brz[col + 1];
                float v00 = 1.0f / (1.0f + expf(-(acc2[i][j][0] + b0)));
                float v01 = 1.0f / (1.0f + expf(-(acc2[i][j][1] + b1)));
                float v10 = 1.0f / (1.0f + expf(-(acc2[i][j][2] + b0)));
                float v11 = 1.0f / (1.0f + expf(-(acc2[i][j][3] + b1)));
                sRZ[row * 132 + (col >> 1)]       = pk2(v00, v01);
                sRZ[(row + 8) * 132 + (col >> 1)] = pk2(v10, v11);
            }
        }
    }
    __syncthreads();

    // ================= Phase 3: GRU candidate + update ========================
    float acc3[2][8][4] = {};
    for (int kb = 0; kb < 256; kb += 32) {
        #pragma unroll
        for (int i = 0; i < 4; i++) {
            int e = tid + i * 128;
            int n = e >> 2, c8 = e & 3;
            uint4 v = *(const uint4*)(Bh + (long)n * 256 + kb + c8 * 8);
            *(uint4*)&sB[n * 20 + c8 * 4] = v;
        }
        __syncthreads();
        const bool lowK = (kb < 128);
        #pragma unroll
        for (int k8 = 0; k8 < 2; k8++) {
            int pb = ((kb & 127) >> 1) + k8 * 8;
            unsigned af[2][4], bf[8][2];
            #pragma unroll
            for (int i = 0; i < 2; i++) {
                int row = wr + i * 16 + g;
                if (lowK) {
                    af[i][0] = sAm[row * 68 + pb + t4];
                    af[i][1] = sAm[(row + 8) * 68 + pb + t4];
                    af[i][2] = sAm[row * 68 + pb + t4 + 4];
                    af[i][3] = sAm[(row + 8) * 68 + pb + t4 + 4];
                } else {
                    af[i][0] = hmul2u(sRZ[row * 132 + pb + t4],       sH[row * 68 + pb + t4]);
                    af[i][1] = hmul2u(sRZ[(row + 8) * 132 + pb + t4], sH[(row + 8) * 68 + pb + t4]);
                    af[i][2] = hmul2u(sRZ[row * 132 + pb + t4 + 4],       sH[row * 68 + pb + t4 + 4]);
                    af[i][3] = hmul2u(sRZ[(row + 8) * 132 + pb + t4 + 4], sH[(row + 8) * 68 + pb + t4 + 4]);
                }
            }
            #pragma unroll
            for (int j = 0; j < 8; j++) {
                int n = wcn + j * 8 + g;
                bf[j][0] = sB[n * 20 + k8 * 8 + t4];
                bf[j][1] = sB[n * 20 + k8 * 8 + t4 + 4];
            }
            #pragma unroll
            for (int i = 0; i < 2; i++)
                #pragma unroll
                for (int j = 0; j < 8; j++)
                    mma_f16(acc3[i][j], af[i], bf[j]);
        }
        __syncthreads();
    }
    #pragma unroll
    for (int i = 0; i < 2; i++) {
        int row = wr + i * 16 + g;
        int gr0 = r0 + row, gr1 = gr0 + 8;
        #pragma unroll
        for (int j = 0; j < 8; j++) {
            int col = wcn + j * 8 + 2 * t4;
            float bb0 = bh[col], bb1 = bh[col + 1];
            unsigned z0u = sRZ[row * 132 + 64 + (col >> 1)];
            unsigned z1u = sRZ[(row + 8) * 132 + 64 + (col >> 1)];
            float2 z0 = __half22float2(*(__half2*)&z0u);
            float2 z1 = __half22float2(*(__half2*)&z1u);
            float2 ho0 = *(const float2*)&hb[(long)gr0 * DD + col];
            float2 ho1 = *(const float2*)&hb[(long)gr1 * DD + col];
            float t00 = tanhf(acc3[i][j][0] + bb0);
            float t01 = tanhf(acc3[i][j][1] + bb1);
            float t10 = tanhf(acc3[i][j][2] + bb0);
            float t11 = tanhf(acc3[i][j][3] + bb1);
            float o00 = (1.0f - z0.x) * ho0.x + z0.x * t00;
            float o01 = (1.0f - z0.y) * ho0.y + z0.y * t01;
            float o10 = (1.0f - z1.x) * ho1.x + z1.x * t10;
            float o11 = (1.0f - z1.y) * ho1.y + z1.y * t11;
            *(float2*)&hob[(long)gr0 * DD + col] = make_float2(o00, o01);
            *(float2*)&hob[(long)gr1 * DD + col] = make_float2(o10, o11);
            hTob[(long)col * NN + gr0] = o00;
            hTob[(long)(col + 1) * NN + gr0] = o01;
            hTob[(long)col * NN + gr1] = o10;
            hTob[(long)(col + 1) * NN + gr1] = o11;
        }
    }
}

// ---------------- final classifier --------------------------------------------
__global__ __launch_bounds__(256) void fc_kernel(
    const float* __restrict__ h, const float* __restrict__ W,
    const float* __restrict__ bfc, float* __restrict__ out)
{
    int b = blockIdx.x, c = blockIdx.y;
    float s = 0.0f;
    for (int i = threadIdx.x; i < NN * DD; i += 256)
        s += h[(long)b * NN * DD + i] * W[(long)i * NCLS + c];
    #pragma unroll
    for (int o = 16; o; o >>= 1) s += __shfl_xor_sync(0xffffffffu, s, o);
    __shared__ float sh[8];
    if ((threadIdx.x & 31) == 0) sh[threadIdx.x >> 5] = s;
    __syncthreads();
    if (threadIdx.x == 0) {
        float t = 0.0f;
        for (int w = 0; w < 8; w++) t += sh[w];
        out[b * NCLS + c] = t + bfc[c];
    }
}

// ---------------- orchestration -----------------------------------------------
extern "C" void kernel_launch(void* const* d_in, const int* in_sizes, int n_in,
                              void* d_out, int out_size)
{
    const float* x        = (const float*)d_in[0];
    const float* supports = (const float*)d_in[1];
    const float* Wgl      = (const float*)d_in[2];
    const float* Wa       = (const float*)d_in[3];
    const float* ba       = (const float*)d_in[4];
    const float* Wr       = (const float*)d_in[5];
    const float* br       = (const float*)d_in[6];
    const float* Wz       = (const float*)d_in[7];
    const float* bz       = (const float*)d_in[8];
    const float* Wh       = (const float*)d_in[9];
    const float* bh       = (const float*)d_in[10];
    const float* Wfc      = (const float*)d_in[11];
    const float* bfc      = (const float*)d_in[12];
    float* out            = (float*)d_out;

    float *S, *A0, *h0, *h1, *hT0, *hT1, *xT, *ri, *brz2, *bh2;
    __half *Brz, *Bh_;
    cudaGetSymbolAddress((void**)&S,    g_S);
    cudaGetSymbolAddress((void**)&A0,   g_A0);
    cudaGetSymbolAddress((void**)&h0,   g_h0);
    cudaGetSymbolAddress((void**)&h1,   g_h1);
    cudaGetSymbolAddress((void**)&hT0,  g_hT0);
    cudaGetSymbolAddress((void**)&hT1,  g_hT1);
    cudaGetSymbolAddress((void**)&xT,   g_xT);
    cudaGetSymbolAddress((void**)&ri,   g_ri);
    cudaGetSymbolAddress((void**)&Brz,  g_Brz_h);
    cudaGetSymbolAddress((void**)&Bh_,  g_Bh_h);
    cudaGetSymbolAddress((void**)&brz2, g_brz2);
    cudaGetSymbolAddress((void**)&bh2,  g_bh2);

    const int ATT_SMEM  = 2 * 256 * 20 * 4;                       // 40960
    const int GGNN_SMEM = (64*68 + 64*68 + 64*132 + 256*20 + 64*20) * 4;  // 94208
    static bool attr_set = false;
    if (!attr_set) {
        cudaFuncSetAttribute(ggnn_step, cudaFuncAttributeMaxDynamicSharedMemorySize,
                             GGNN_SMEM);
        attr_set = true;
    }

    prep_kernel<<<386, 256>>>(Wa, Wr, Wz, Wh, ba, br, bz, bh, Brz, Bh_, brz2, bh2);

    // ---- attention for all timesteps, fused normalize+weight ----
    rinv_kernel<<<T_STEPS * BATCH * NN, 128>>>(x, Wgl, ri);
    att_kernel<<<dim3(1, 2, T_STEPS * BATCH), 256, ATT_SMEM>>>(x, Wgl, ri, S);
    reduce_kernel<<<(BATCH * NN * NN / 4) / 256, 256>>>(S, supports, A0);

    // ---- GGNN for last timestep only, one fused kernel per step ----
    const float* xt = x + (long)(T_STEPS - 1) * BATCH * NN * DD;
    transpose_k<<<dim3(8, 4, BATCH), dim3(32, 8)>>>(xt, xT);

    const float* hp  = xt;
    const float* hpT = xT;
    float* hn  = h0;
    float* hnT = hT0;
    for (int s = 0; s < GSTEPS; s++) {
        ggnn_step<<<dim3(4, BATCH), 128, GGNN_SMEM>>>(
            A0, hp, hpT, Brz, brz2, Bh_, bh2, hn, hnT);
        hp = hn; hpT = hnT;
        hn  = (hn == h0) ? h1 : h0;
        hnT = (hnT == hT0) ? hT1 : hT0;
    }

    fc_kernel<<<dim3(BATCH, NCLS), 256>>>(hp, Wfc, bfc, out);
    (void)in_sizes; (void)n_in; (void)out_size;
}

// round 11
// speedup vs baseline: 21.5885x; 1.0484x over previous
#include <cuda_runtime.h>
#include <cuda_fp16.h>
#include <math.h>
#include <stdint.h>

#define T_STEPS 16
#define BATCH   32
#define NN      256
#define DD      128
#define HEADS   16
#define KGL     (HEADS*DD)
#define GSTEPS  5
#define NCLS    2
#define SKIPW   0.3f
#define EPSV    1e-8f

// ---------------- scratch (device globals; no allocation allowed) ------------
__device__ __half g_S [(long)T_STEPS*BATCH*NN*NN];   // weighted-normalized att (fp16)
__device__ float g_A0 [(long)BATCH*NN*NN];           // A_final
__device__ float g_h0 [(long)BATCH*NN*DD];
__device__ float g_h1 [(long)BATCH*NN*DD];
__device__ float g_hT0[(long)BATCH*NN*DD];
__device__ float g_hT1[(long)BATCH*NN*DD];
__device__ float g_xT [(long)BATCH*NN*DD];
__device__ float g_ri [(long)T_STEPS*BATCH*NN*HEADS];
__device__ __half g_Brz_h[2*DD*2*DD];   // (N=256,K=256) row-major, Wa folded into k<128
__device__ __half g_Bh_h [DD*2*DD];     // (N=128,K=256) row-major
__device__ float  g_brz2[2*DD];
__device__ float  g_bh2 [DD];

// ---------------- fp16 helpers -------------------------------------------------
__device__ __forceinline__ unsigned pk2(float a, float b) {
    __half2 h = __floats2half2_rn(a, b);
    return *(unsigned*)&h;
}
__device__ __forceinline__ uint2 pk4(float4 v) {
    return make_uint2(pk2(v.x, v.y), pk2(v.z, v.w));
}
__device__ __forceinline__ unsigned hmul2u(unsigned a, unsigned b) {
    __half2 r = __hmul2(*(__half2*)&a, *(__half2*)&b);
    return *(unsigned*)&r;
}
__device__ __forceinline__ void mma_f16(float c[4], const unsigned a[4], const unsigned b[2]) {
    asm volatile(
        "mma.sync.aligned.m16n8k16.row.col.f32.f16.f16.f32 "
        "{%0,%1,%2,%3}, {%4,%5,%6,%7}, {%8,%9}, {%0,%1,%2,%3};\n"
        : "+f"(c[0]), "+f"(c[1]), "+f"(c[2]), "+f"(c[3])
        : "r"(a[0]), "r"(a[1]), "r"(a[2]), "r"(a[3]), "r"(b[0]), "r"(b[1]));
}

// ---------------- rinv: 0.25/(||x*w_h|| + eps) ---------------------------------
__global__ __launch_bounds__(128) void rinv_kernel(
    const float* __restrict__ x, const float* __restrict__ Wgl, float* __restrict__ rinv)
{
    long node = blockIdx.x;
    int tid = threadIdx.x, lane = tid & 31, w = tid >> 5;
    __shared__ float xs[DD];
    xs[tid] = x[node * DD + tid];
    __syncthreads();
    float4 xv = *(const float4*)&xs[lane * 4];
    #pragma unroll
    for (int hh = 0; hh < 4; hh++) {
        int h = w * 4 + hh;
        float4 wv = *(const float4*)&Wgl[h * DD + lane * 4];
        float a = xv.x * wv.x, b = xv.y * wv.y, c = xv.z * wv.z, d = xv.w * wv.w;
        float ss = a*a + b*b + c*c + d*d;
        #pragma unroll
        for (int o = 16; o; o >>= 1) ss += __shfl_xor_sync(0xffffffffu, ss, o);
        if (lane == 0) rinv[node * HEADS + h] = 0.25f / (sqrtf(ss) + EPSV);
    }
}

// ---------------- fused attention (fp16 MMA, smem-resident operands) -----------
// smem layout (uints): [0, 5120) Vtile stage0; [5120,10240) stage1;
//   [10240, 26880) x fp16 pairs 256 x 65; [26880, 30976) rinv fp32 256x16;
//   [30976, 33024) Wgl fp32 2048.
#define ATT_SMEM_UINTS 33024
__global__ __launch_bounds__(256, 1) void att_kernel(
    const float* __restrict__ x, const float* __restrict__ Wgl,
    const float* __restrict__ rinv, __half* __restrict__ S)
{
    extern __shared__ __align__(16) unsigned smA[];
    unsigned* sV0 = smA;
    unsigned* sV1 = smA + 5120;
    unsigned* sX  = smA + 10240;          // stride 65 uints per node (scalar access only)
    float*    sR  = (float*)(smA + 26880);
    float*    sW  = (float*)(smA + 30976);

    const int tid = threadIdx.x;
    const int lane = tid & 31, wid = tid >> 5;
    const int g = lane >> 2, t4 = lane & 3;
    const int wr = (wid >> 2) * 64;
    const int wc = (wid & 3) * 64;
    const int bz = blockIdx.z;
    const int rowBase = blockIdx.y * 128;

    const float* xb = x + (long)bz * NN * DD;
    const float* rb = rinv + (long)bz * NN * HEADS;
    __half* Sb = S + (long)bz * NN * NN;

    const int myN = tid >> 3;
    const int c4  = tid & 7;

    // ---- stage x (fp16), rinv, Wgl into smem ----
    #pragma unroll
    for (int it = 0; it < 32; it++) {
        int e = tid + it * 256;
        int n = e >> 5, c = e & 31;
        float4 v = *(const float4*)&xb[(long)n * DD + c * 4];
        sX[n * 65 + c * 2]     = pk2(v.x, v.y);
        sX[n * 65 + c * 2 + 1] = pk2(v.z, v.w);
    }
    #pragma unroll
    for (int it = 0; it < 4; it++) {
        int e = tid + it * 256;
        ((float4*)sR)[e] = ((const float4*)rb)[e];
    }
    #pragma unroll
    for (int it = 0; it < 2; it++) {
        int e = tid + it * 256;
        ((float4*)sW)[e] = ((const float4*)Wgl)[e];
    }
    __syncthreads();

    float acc[4][8][4] = {};

    // synth one 256x32 V tile at k-offset kb into buf (scalar 32-bit LDS only)
    auto synth = [&](unsigned* buf, int kb) {
        int h = kb >> 7;
        int dof = (kb & 127) + c4 * 4;
        float4 ws = *(const float4*)&sW[kb + c4 * 4];
        #pragma unroll
        for (int it = 0; it < 8; it++) {
            int n = myN + it * 32;
            float rn = sR[n * 16 + h];
            int base = n * 65 + (dof >> 1);
            unsigned xp0 = sX[base];          // 4-byte aligned scalar loads
            unsigned xp1 = sX[base + 1];
            float2 x01 = __half22float2(*(__half2*)&xp0);
            float2 x23 = __half22float2(*(__half2*)&xp1);
            buf[n * 20 + c4 * 2]     = pk2(x01.x * ws.x * rn, x01.y * ws.y * rn);
            buf[n * 20 + c4 * 2 + 1] = pk2(x23.x * ws.z * rn, x23.y * ws.w * rn);
        }
    };

    synth(sV0, 0);
    __syncthreads();

    unsigned* cur = sV0; unsigned* nxt = sV1;
    for (int kbi = 0; kbi < KGL / 32; kbi++) {
        #pragma unroll
        for (int k8 = 0; k8 < 2; k8++) {
            unsigned af[4][4], bf[8][2];
            #pragma unroll
            for (int i = 0; i < 4; i++) {
                int r = rowBase + wr + i * 16 + g;
                af[i][0] = cur[r * 20 + k8 * 8 + t4];
                af[i][1] = cur[(r + 8) * 20 + k8 * 8 + t4];
                af[i][2] = cur[r * 20 + k8 * 8 + t4 + 4];
                af[i][3] = cur[(r + 8) * 20 + k8 * 8 + t4 + 4];
            }
            #pragma unroll
            for (int j = 0; j < 8; j++) {
                int n = wc + j * 8 + g;
                bf[j][0] = cur[n * 20 + k8 * 8 + t4];
                bf[j][1] = cur[n * 20 + k8 * 8 + t4 + 4];
            }
            #pragma unroll
            for (int i = 0; i < 4; i++)
                #pragma unroll
                for (int j = 0; j < 8; j++)
                    mma_f16(acc[i][j], af[i], bf[j]);
        }
        if (kbi + 1 < KGL / 32) synth(nxt, (kbi + 1) * 32);
        __syncthreads();
        unsigned* tmp = cur; cur = nxt; nxt = tmp;
    }

    // ---- epilogue: relu, cross-warp rowsum, normalize, weight, store fp16 ----
    float* rsm = (float*)smA;                  // [128][5]
    int t = bz >> 5;
    float wt = 0.7f * powf(SKIPW, (float)(T_STEPS - 1 - t));

    #pragma unroll
    for (int i = 0; i < 4; i++)
        #pragma unroll
        for (int j = 0; j < 8; j++)
            #pragma unroll
            for (int v = 0; v < 4; v++) acc[i][j][v] = fmaxf(acc[i][j][v], 0.0f);

    #pragma unroll
    for (int i = 0; i < 4; i++) {
        float s0 = 0.0f, s1 = 0.0f;
        #pragma unroll
        for (int j = 0; j < 8; j++) {
            s0 += acc[i][j][0] + acc[i][j][1];
            s1 += acc[i][j][2] + acc[i][j][3];
        }
        s0 += __shfl_xor_sync(0xffffffffu, s0, 1);
        s0 += __shfl_xor_sync(0xffffffffu, s0, 2);
        s1 += __shfl_xor_sync(0xffffffffu, s1, 1);
        s1 += __shfl_xor_sync(0xffffffffu, s1, 2);
        if (t4 == 0) {
            rsm[(wr + i * 16 + g) * 5 + (wid & 3)] = s0;
            rsm[(wr + i * 16 + g + 8) * 5 + (wid & 3)] = s1;
        }
    }
    __syncthreads();
    #pragma unroll
    for (int i = 0; i < 4; i++) {
        int r0 = wr + i * 16 + g, r1 = r0 + 8;
        float tot0 = rsm[r0*5+0] + rsm[r0*5+1] + rsm[r0*5+2] + rsm[r0*5+3];
        float tot1 = rsm[r1*5+0] + rsm[r1*5+1] + rsm[r1*5+2] + rsm[r1*5+3];
        float inv0 = wt / (tot0 + EPSV);
        float inv1 = wt / (tot1 + EPSV);
        #pragma unroll
        for (int j = 0; j < 8; j++) {
            int c0 = wc + j * 8 + t4 * 2;
            *(unsigned*)&Sb[(long)(rowBase + r0) * NN + c0] =
                pk2(acc[i][j][0] * inv0, acc[i][j][1] * inv0);
            *(unsigned*)&Sb[(long)(rowBase + r1) * NN + c0] =
                pk2(acc[i][j][2] * inv1, acc[i][j][3] * inv1);
        }
    }
}

// ---------------- A = 0.3^16 * supports + sum_t S_t (fp16 in, fp32 out) --------
__global__ __launch_bounds__(256) void reduce_kernel(
    const __half* __restrict__ S, const float* __restrict__ sup, float* __restrict__ A)
{
    long i4 = (long)blockIdx.x * 256 + threadIdx.x;   // over B*N*N/4
    const uint2* S2 = (const uint2*)S;
    const float4* P4 = (const float4*)sup;
    float4* A4 = (float4*)A;
    int b = (int)(i4 >> 14);
    long rem = i4 & 16383;
    const float k16 = 4.3046721e-8f;
    float4 p = P4[i4];
    float4 a = make_float4(p.x * k16, p.y * k16, p.z * k16, p.w * k16);
    #pragma unroll
    for (int t = 0; t < T_STEPS; t++) {
        uint2 v = S2[(((long)(t * BATCH + b)) << 14) + rem];
        float2 v01 = __half22float2(*(__half2*)&v.x);
        float2 v23 = __half22float2(*(__half2*)&v.y);
        a.x += v01.x; a.y += v01.y; a.z += v23.x; a.w += v23.y;
    }
    A4[i4] = a;
}

// ------- prep: fold Wa/ba into gate weights; output fp16 (N,K) blocks ----------
__global__ void prep_kernel(
    const float* __restrict__ Wa, const float* __restrict__ Wr,
    const float* __restrict__ Wz, const float* __restrict__ Wh,
    const float* __restrict__ ba, const float* __restrict__ br,
    const float* __restrict__ bz, const float* __restrict__ bh,
    __half* __restrict__ Brz, __half* __restrict__ Bh_,
    float* __restrict__ brz2, float* __restrict__ bh2)
{
    int idx = blockIdx.x * blockDim.x + threadIdx.x;
    if (idx < 65536) {
        int n = idx >> 8, k = idx & 255, np = n & 127;
        const float* W = (n < 128) ? Wr : Wz;
        float v;
        if (k < 128) {
            v = 0.0f;
            for (int d = 0; d < 128; d++) v += Wa[k * 128 + d] * W[d * 128 + np];
        } else v = W[k * 128 + np];
        Brz[n * 256 + k] = __float2half(v);
    } else if (idx < 98304) {
        int e = idx - 65536, n = e >> 8, k = e & 255;
        float v;
        if (k < 128) {
            v = 0.0f;
            for (int d = 0; d < 128; d++) v += Wa[k * 128 + d] * Wh[d * 128 + n];
        } else v = Wh[k * 128 + n];
        Bh_[n * 256 + k] = __float2half(v);
    } else if (idx < 98560) {
        int n = idx - 98304, np = n & 127;
        const float* W = (n < 128) ? Wr : Wz;
        float v = (n < 128) ? br[np] : bz[np];
        for (int d = 0; d < 128; d++) v += ba[d] * W[d * 128 + np];
        brz2[n] = v;
    } else if (idx < 98688) {
        int n = idx - 98560;
        float v = bh[n];
        for (int d = 0; d < 128; d++) v += ba[d] * Wh[d * 128 + n];
        bh2[n] = v;
    }
}

// ---------------- per-batch (N,D) -> (D,N) transpose ---------------------------
__global__ void transpose_k(const float* __restrict__ src, float* __restrict__ dst)
{
    __shared__ float tile[32][33];
    int b = blockIdx.z;
    int n0 = blockIdx.x * 32, d0 = blockIdx.y * 32;
    const float* s = src + (long)b * NN * DD;
    float* o = dst + (long)b * NN * DD;
    #pragma unroll
    for (int k = 0; k < 4; k++)
        tile[threadIdx.y + k * 8][threadIdx.x] =
            s[(long)(n0 + threadIdx.y + k * 8) * DD + d0 + threadIdx.x];
    __syncthreads();
    #pragma unroll
    for (int k = 0; k < 4; k++)
        o[(long)(d0 + threadIdx.y + k * 8) * NN + n0 + threadIdx.x] =
            tile[threadIdx.x][threadIdx.y + k * 8];
}

// ---------------- fully fused GGNN step (256 threads, 8 warps) -----------------
__global__ __launch_bounds__(256) void ggnn_step(
    const float* __restrict__ A, const float* __restrict__ h_in,
    const float* __restrict__ hT_in,
    const __half* __restrict__ Brz, const float* __restrict__ brz,
    const __half* __restrict__ Bh, const float* __restrict__ bh,
    float* __restrict__ h_out, float* __restrict__ hT_out)
{
    extern __shared__ __align__(16) unsigned smG[];
    unsigned* sAm = smG;                  // [64][68]
    unsigned* sH  = sAm + 64 * 68;        // [64][68]
    unsigned* sRZ = sH  + 64 * 68;        // [64][132]
    unsigned* sB  = sRZ + 64 * 132;       // stream buffer (max [256][20])
    unsigned* sA1 = sB  + 256 * 20;       // [64][20]

    const int tid = threadIdx.x, lane = tid & 31, wid = tid >> 5;
    const int g = lane >> 2, t4 = lane & 3;
    const int b = blockIdx.y, r0 = blockIdx.x * 64;
    const int wr = (wid >> 1) * 16;       // 4 row groups of 16
    const int wcn = (wid & 1) * 64;

    const float* Ab  = A + (long)b * NN * NN;
    const float* hb  = h_in + (long)b * NN * DD;
    const float* hTb = hT_in + (long)b * NN * DD;
    float* hob  = h_out + (long)b * NN * DD;
    float* hTob = hT_out + (long)b * NN * DD;

    #pragma unroll
    for (int i = 0; i < 8; i++) {
        int e = tid + i * 256;
        int r = e >> 5, c4 = e & 31;
        float4 v = *(const float4*)&hb[(long)(r0 + r) * DD + c4 * 4];
        *(uint2*)&sH[r * 68 + c4 * 2] = pk4(v);
    }

    // ================= Phase 1: am = A @ h =================
    float acc1[8][4] = {};
    for (int kb = 0; kb < 256; kb += 32) {
        #pragma unroll
        for (int i = 0; i < 2; i++) {
            int e = tid + i * 256;
            int r = e >> 3, c4 = e & 7;
            float4 v = *(const float4*)&Ab[(long)(r0 + r) * NN + kb + c4 * 4];
            *(uint2*)&sA1[r * 20 + c4 * 2] = pk4(v);
        }
        #pragma unroll
        for (int i = 0; i < 4; i++) {
            int e = tid + i * 256;
            int d = e >> 3, nq = e & 7;
            float4 v = *(const float4*)&hTb[(long)d * NN + kb + nq * 4];
            *(uint2*)&sB[d * 18 + nq * 2] = pk4(v);
        }
        __syncthreads();
        #pragma unroll
        for (int k8 = 0; k8 < 2; k8++) {
            unsigned af[4], bf[8][2];
            int row = wr + g;
            af[0] = sA1[row * 20 + k8 * 8 + t4];
            af[1] = sA1[(row + 8) * 20 + k8 * 8 + t4];
            af[2] = sA1[row * 20 + k8 * 8 + t4 + 4];
            af[3] = sA1[(row + 8) * 20 + k8 * 8 + t4 + 4];
            #pragma unroll
            for (int j = 0; j < 8; j++) {
                int n = wcn + j * 8 + g;
                bf[j][0] = sB[n * 18 + k8 * 8 + t4];
                bf[j][1] = sB[n * 18 + k8 * 8 + t4 + 4];
            }
            #pragma unroll
            for (int j = 0; j < 8; j++)
                mma_f16(acc1[j], af, bf[j]);
        }
        __syncthreads();
    }
    {
        int row = wr + g;
        #pragma unroll
        for (int j = 0; j < 8; j++) {
            int colp = ((wcn + j * 8) >> 1) + t4;
            sAm[row * 68 + colp]       = pk2(acc1[j][0], acc1[j][1]);
            sAm[(row + 8) * 68 + colp] = pk2(acc1[j][2], acc1[j][3]);
        }
    }
    __syncthreads();

    // ================= Phase 2: [r|z] = sigmoid([am|h] @ Brz + brz2) ==========
    {
        const int wc2 = (wid & 1) * 128;
        float acc2[16][4] = {};
        for (int kb = 0; kb < 256; kb += 32) {
            #pragma unroll
            for (int i = 0; i < 4; i++) {
                int e = tid + i * 256;
                int n = e >> 2, c8 = e & 3;
                uint4 v = *(const uint4*)(Brz + (long)n * 256 + kb + c8 * 8);
                *(uint4*)&sB[n * 20 + c8 * 4] = v;
            }
            __syncthreads();
            const unsigned* src = (kb < 128) ? sAm : sH;
            #pragma unroll
            for (int k8 = 0; k8 < 2; k8++) {
                int pb = ((kb & 127) >> 1) + k8 * 8;
                unsigned af[4], bf[16][2];
                int row = wr + g;
                af[0] = src[row * 68 + pb + t4];
                af[1] = src[(row + 8) * 68 + pb + t4];
                af[2] = src[row * 68 + pb + t4 + 4];
                af[3] = src[(row + 8) * 68 + pb + t4 + 4];
                #pragma unroll
                for (int j = 0; j < 16; j++) {
                    int n = wc2 + j * 8 + g;
                    bf[j][0] = sB[n * 20 + k8 * 8 + t4];
                    bf[j][1] = sB[n * 20 + k8 * 8 + t4 + 4];
                }
                #pragma unroll
                for (int j = 0; j < 16; j++)
                    mma_f16(acc2[j], af, bf[j]);
            }
            __syncthreads();
        }
        {
            int row = wr + g;
            #pragma unroll
            for (int j = 0; j < 16; j++) {
                int col = wc2 + j * 8 + 2 * t4;
                float b0 = brz[col], b1 = brz[col + 1];
                float v00 = 1.0f / (1.0f + expf(-(acc2[j][0] + b0)));
                float v01 = 1.0f / (1.0f + expf(-(acc2[j][1] + b1)));
                float v10 = 1.0f / (1.0f + expf(-(acc2[j][2] + b0)));
                float v11 = 1.0f / (1.0f + expf(-(acc2[j][3] + b1)));
                sRZ[row * 132 + (col >> 1)]       = pk2(v00, v01);
                sRZ[(row + 8) * 132 + (col >> 1)] = pk2(v10, v11);
            }
        }
    }
    __syncthreads();

    // ================= Phase 3: GRU candidate + update ========================
    float acc3[8][4] = {};
    for (int kb = 0; kb < 256; kb += 32) {
        #pragma unroll
        for (int i = 0; i < 2; i++) {
            int e = tid + i * 256;
            int n = e >> 2, c8 = e & 3;
            uint4 v = *(const uint4*)(Bh + (long)n * 256 + kb + c8 * 8);
            *(uint4*)&sB[n * 20 + c8 * 4] = v;
        }
        __syncthreads();
        const bool lowK = (kb < 128);
        #pragma unroll
        for (int k8 = 0; k8 < 2; k8++) {
            int pb = ((kb & 127) >> 1) + k8 * 8;
            unsigned af[4], bf[8][2];
            int row = wr + g;
            if (lowK) {
                af[0] = sAm[row * 68 + pb + t4];
                af[1] = sAm[(row + 8) * 68 + pb + t4];
                af[2] = sAm[row * 68 + pb + t4 + 4];
                af[3] = sAm[(row + 8) * 68 + pb + t4 + 4];
            } else {
                af[0] = hmul2u(sRZ[row * 132 + pb + t4],       sH[row * 68 + pb + t4]);
                af[1] = hmul2u(sRZ[(row + 8) * 132 + pb + t4], sH[(row + 8) * 68 + pb + t4]);
                af[2] = hmul2u(sRZ[row * 132 + pb + t4 + 4],       sH[row * 68 + pb + t4 + 4]);
                af[3] = hmul2u(sRZ[(row + 8) * 132 + pb + t4 + 4], sH[(row + 8) * 68 + pb + t4 + 4]);
            }
            #pragma unroll
            for (int j = 0; j < 8; j++) {
                int n = wcn + j * 8 + g;
                bf[j][0] = sB[n * 20 + k8 * 8 + t4];
                bf[j][1] = sB[n * 20 + k8 * 8 + t4 + 4];
            }
            #pragma unroll
            for (int j = 0; j < 8; j++)
                mma_f16(acc3[j], af, bf[j]);
        }
        __syncthreads();
    }
    {
        int row = wr + g;
        int gr0 = r0 + row, gr1 = gr0 + 8;
        #pragma unroll
        for (int j = 0; j < 8; j++) {
            int col = wcn + j * 8 + 2 * t4;
            float bb0 = bh[col], bb1 = bh[col + 1];
            unsigned z0u = sRZ[row * 132 + 64 + (col >> 1)];
            unsigned z1u = sRZ[(row + 8) * 132 + 64 + (col >> 1)];
            float2 z0 = __half22float2(*(__half2*)&z0u);
            float2 z1 = __half22float2(*(__half2*)&z1u);
            float2 ho0 = *(const float2*)&hb[(long)gr0 * DD + col];
            float2 ho1 = *(const float2*)&hb[(long)gr1 * DD + col];
            float t00 = tanhf(acc3[j][0] + bb0);
            float t01 = tanhf(acc3[j][1] + bb1);
            float t10 = tanhf(acc3[j][2] + bb0);
            float t11 = tanhf(acc3[j][3] + bb1);
            float o00 = (1.0f - z0.x) * ho0.x + z0.x * t00;
            float o01 = (1.0f - z0.y) * ho0.y + z0.y * t01;
            float o10 = (1.0f - z1.x) * ho1.x + z1.x * t10;
            float o11 = (1.0f - z1.y) * ho1.y + z1.y * t11;
            *(float2*)&hob[(long)gr0 * DD + col] = make_float2(o00, o01);
            *(float2*)&hob[(long)gr1 * DD + col] = make_float2(o10, o11);
            hTob[(long)col * NN + gr0] = o00;
            hTob[(long)(col + 1) * NN + gr0] = o01;
            hTob[(long)col * NN + gr1] = o10;
            hTob[(long)(col + 1) * NN + gr1] = o11;
        }
    }
}

// ---------------- final classifier --------------------------------------------
__global__ __launch_bounds__(256) void fc_kernel(
    const float* __restrict__ h, const float* __restrict__ W,
    const float* __restrict__ bfc, float* __restrict__ out)
{
    int b = blockIdx.x, c = blockIdx.y;
    float s = 0.0f;
    for (int i = threadIdx.x; i < NN * DD; i += 256)
        s += h[(long)b * NN * DD + i] * W[(long)i * NCLS + c];
    #pragma unroll
    for (int o = 16; o; o >>= 1) s += __shfl_xor_sync(0xffffffffu, s, o);
    __shared__ float sh[8];
    if ((threadIdx.x & 31) == 0) sh[threadIdx.x >> 5] = s;
    __syncthreads();
    if (threadIdx.x == 0) {
        float t = 0.0f;
        for (int w = 0; w < 8; w++) t += sh[w];
        out[b * NCLS + c] = t + bfc[c];
    }
}

// ---------------- orchestration -----------------------------------------------
extern "C" void kernel_launch(void* const* d_in, const int* in_sizes, int n_in,
                              void* d_out, int out_size)
{
    const float* x        = (const float*)d_in[0];
    const float* supports = (const float*)d_in[1];
    const float* Wgl      = (const float*)d_in[2];
    const float* Wa       = (const float*)d_in[3];
    const float* ba       = (const float*)d_in[4];
    const float* Wr       = (const float*)d_in[5];
    const float* br       = (const float*)d_in[6];
    const float* Wz       = (const float*)d_in[7];
    const float* bz       = (const float*)d_in[8];
    const float* Wh       = (const float*)d_in[9];
    const float* bh       = (const float*)d_in[10];
    const float* Wfc      = (const float*)d_in[11];
    const float* bfc      = (const float*)d_in[12];
    float* out            = (float*)d_out;

    float *A0, *h0, *h1, *hT0, *hT1, *xT, *ri, *brz2, *bh2;
    __half *S, *Brz, *Bh_;
    cudaGetSymbolAddress((void**)&S,    g_S);
    cudaGetSymbolAddress((void**)&A0,   g_A0);
    cudaGetSymbolAddress((void**)&h0,   g_h0);
    cudaGetSymbolAddress((void**)&h1,   g_h1);
    cudaGetSymbolAddress((void**)&hT0,  g_hT0);
    cudaGetSymbolAddress((void**)&hT1,  g_hT1);
    cudaGetSymbolAddress((void**)&xT,   g_xT);
    cudaGetSymbolAddress((void**)&ri,   g_ri);
    cudaGetSymbolAddress((void**)&Brz,  g_Brz_h);
    cudaGetSymbolAddress((void**)&Bh_,  g_Bh_h);
    cudaGetSymbolAddress((void**)&brz2, g_brz2);
    cudaGetSymbolAddress((void**)&bh2,  g_bh2);

    const int ATT_SMEM  = ATT_SMEM_UINTS * 4;                     // 132096
    const int GGNN_SMEM = (64*68 + 64*68 + 64*132 + 256*20 + 64*20) * 4;  // 94208
    static bool attr_set = false;
    if (!attr_set) {
        cudaFuncSetAttribute(att_kernel, cudaFuncAttributeMaxDynamicSharedMemorySize,
                             ATT_SMEM);
        cudaFuncSetAttribute(ggnn_step, cudaFuncAttributeMaxDynamicSharedMemorySize,
                             GGNN_SMEM);
        attr_set = true;
    }

    prep_kernel<<<386, 256>>>(Wa, Wr, Wz, Wh, ba, br, bz, bh, Brz, Bh_, brz2, bh2);

    // ---- attention for all timesteps, fused normalize+weight, fp16 out ----
    rinv_kernel<<<T_STEPS * BATCH * NN, 128>>>(x, Wgl, ri);
    att_kernel<<<dim3(1, 2, T_STEPS * BATCH), 256, ATT_SMEM>>>(x, Wgl, ri, S);
    reduce_kernel<<<(BATCH * NN * NN / 4) / 256, 256>>>(S, supports, A0);

    // ---- GGNN for last timestep only, one fused kernel per step ----
    const float* xt = x + (long)(T_STEPS - 1) * BATCH * NN * DD;
    transpose_k<<<dim3(8, 4, BATCH), dim3(32, 8)>>>(xt, xT);

    const float* hp  = xt;
    const float* hpT = xT;
    float* hn  = h0;
    float* hnT = hT0;
    for (int s = 0; s < GSTEPS; s++) {
        ggnn_step<<<dim3(4, BATCH), 256, GGNN_SMEM>>>(
            A0, hp, hpT, Brz, brz2, Bh_, bh2, hn, hnT);
        hp = hn; hpT = hnT;
        hn  = (hn == h0) ? h1 : h0;
        hnT = (hnT == hT0) ? hT1 : hT0;
    }

    fc_kernel<<<dim3(BATCH, NCLS), 256>>>(hp, Wfc, bfc, out);
    (void)in_sizes; (void)n_in; (void)out_size;
}

// round 13
// speedup vs baseline: 23.4638x; 1.0869x over previous
#include <cuda_runtime.h>
#include <cuda_fp16.h>
#include <math.h>
#include <stdint.h>

#define T_STEPS 16
#define BATCH   32
#define NN      256
#define DD      128
#define HEADS   16
#define KGL     (HEADS*DD)
#define GSTEPS  5
#define NCLS    2
#define SKIPW   0.3f
#define EPSV    1e-8f

// ---------------- scratch (device globals; no allocation allowed) ------------
__device__ __half g_S [(long)T_STEPS*BATCH*NN*NN];   // RAW relu(V V^T) fp16
__device__ float g_A0 [(long)BATCH*NN*NN];           // A_final
__device__ float g_h0 [(long)BATCH*NN*DD];
__device__ float g_h1 [(long)BATCH*NN*DD];
__device__ float g_hT0[(long)BATCH*NN*DD];
__device__ float g_hT1[(long)BATCH*NN*DD];
__device__ float g_xT [(long)BATCH*NN*DD];
__device__ float g_ri [(long)T_STEPS*BATCH*NN*HEADS];
__device__ float g_rsA[(long)T_STEPS*BATCH*NN];      // rowsums (n<128) + Q01 colsums (n>=128)
__device__ float g_rsB[(long)T_STEPS*BATCH*NN];      // Q11 rowsums (n>=128)
__device__ float g_inv[(long)T_STEPS*BATCH*NN];      // wt/(rowsum+eps)
__device__ __half g_Brz_h[2*DD*2*DD];
__device__ __half g_Bh_h [DD*2*DD];
__device__ float  g_brz2[2*DD];
__device__ float  g_bh2 [DD];

// ---------------- fp16 helpers -------------------------------------------------
__device__ __forceinline__ unsigned pk2(float a, float b) {
    __half2 h = __floats2half2_rn(a, b);
    return *(unsigned*)&h;
}
__device__ __forceinline__ uint2 pk4(float4 v) {
    return make_uint2(pk2(v.x, v.y), pk2(v.z, v.w));
}
__device__ __forceinline__ unsigned hmul2u(unsigned a, unsigned b) {
    __half2 r = __hmul2(*(__half2*)&a, *(__half2*)&b);
    return *(unsigned*)&r;
}
__device__ __forceinline__ void mma_f16(float c[4], const unsigned a[4], const unsigned b[2]) {
    asm volatile(
        "mma.sync.aligned.m16n8k16.row.col.f32.f16.f16.f32 "
        "{%0,%1,%2,%3}, {%4,%5,%6,%7}, {%8,%9}, {%0,%1,%2,%3};\n"
        : "+f"(c[0]), "+f"(c[1]), "+f"(c[2]), "+f"(c[3])
        : "r"(a[0]), "r"(a[1]), "r"(a[2]), "r"(a[3]), "r"(b[0]), "r"(b[1]));
}

// ---------------- rinv: 0.25/(||x*w_h|| + eps) ---------------------------------
__global__ __launch_bounds__(128) void rinv_kernel(
    const float* __restrict__ x, const float* __restrict__ Wgl, float* __restrict__ rinv)
{
    long node = blockIdx.x;
    int tid = threadIdx.x, lane = tid & 31, w = tid >> 5;
    __shared__ float xs[DD];
    xs[tid] = x[node * DD + tid];
    __syncthreads();
    float4 xv = *(const float4*)&xs[lane * 4];
    #pragma unroll
    for (int hh = 0; hh < 4; hh++) {
        int h = w * 4 + hh;
        float4 wv = *(const float4*)&Wgl[h * DD + lane * 4];
        float a = xv.x * wv.x, b = xv.y * wv.y, c = xv.z * wv.z, d = xv.w * wv.w;
        float ss = a*a + b*b + c*c + d*d;
        #pragma unroll
        for (int o = 16; o; o >>= 1) ss += __shfl_xor_sync(0xffffffffu, ss, o);
        if (lane == 0) rinv[node * HEADS + h] = 0.25f / (sqrtf(ss) + EPSV);
    }
}

// ============ attention kernel A: rows 0-127 x cols 0-255 (Q00+Q01) ============
// Stores raw relu fp16 direct + mirrored Q01^T into rows 128-255 cols 0-127.
// Writes rsA: [n<128] full rowsums; [n>=128] Q01 colsums.
#define AT_ST0   0
#define AT_ST1   5120
#define AT_SX    10240      // 256 x 65 uints
#define AT_SR    26880      // 4096 floats
#define AT_SW    30976      // 2048 floats
#define AT_UINTS 33024
#define ATTA_BYTES (AT_UINTS * 4)

__global__ __launch_bounds__(256, 1) void att_a_kernel(
    const float* __restrict__ x, const float* __restrict__ Wgl,
    const float* __restrict__ rinv, __half* __restrict__ S,
    float* __restrict__ rsA)
{
    extern __shared__ __align__(16) unsigned smA[];
    unsigned* sX = smA + AT_SX;
    float* sR = (float*)(smA + AT_SR);
    float* sW = (float*)(smA + AT_SW);

    const int tid = threadIdx.x;
    const int lane = tid & 31, wid = tid >> 5;
    const int g = lane >> 2, t4 = lane & 3;
    const int wr = (wid >> 2) * 64;            // {0,64}
    const int wc = (wid & 3) * 64;             // {0,64,128,192}
    const int bz = blockIdx.x;

    const float* xb = x + (long)bz * NN * DD;
    const float* rb = rinv + (long)bz * NN * HEADS;
    __half* Sb = S + (long)bz * NN * NN;

    const int myN = tid >> 3;
    const int c4  = tid & 7;

    #pragma unroll
    for (int it = 0; it < 32; it++) {
        int e = tid + it * 256, n = e >> 5, c = e & 31;
        float4 v = *(const float4*)&xb[(long)n * DD + c * 4];
        sX[n * 65 + c * 2]     = pk2(v.x, v.y);
        sX[n * 65 + c * 2 + 1] = pk2(v.z, v.w);
    }
    #pragma unroll
    for (int it = 0; it < 4; it++)
        ((float4*)sR)[tid + it * 256] = ((const float4*)rb)[tid + it * 256];
    #pragma unroll
    for (int it = 0; it < 2; it++)
        ((float4*)sW)[tid + it * 256] = ((const float4*)Wgl)[tid + it * 256];
    __syncthreads();

    float acc[4][8][4] = {};

    auto synth = [&](unsigned* buf, int kb) {
        int h = kb >> 7;
        int dof = (kb & 127) + c4 * 4;
        float4 ws = *(const float4*)&sW[kb + c4 * 4];
        #pragma unroll
        for (int it = 0; it < 8; it++) {
            int n = myN + it * 32;
            float rn = sR[n * 16 + h];
            int base = n * 65 + (dof >> 1);
            unsigned x0 = sX[base], x1 = sX[base + 1];
            float2 a = __half22float2(*(__half2*)&x0);
            float2 b = __half22float2(*(__half2*)&x1);
            buf[n * 20 + c4 * 2]     = pk2(a.x * ws.x * rn, a.y * ws.y * rn);
            buf[n * 20 + c4 * 2 + 1] = pk2(b.x * ws.z * rn, b.y * ws.w * rn);
        }
    };

    unsigned* B0 = smA + AT_ST0;
    unsigned* B1 = smA + AT_ST1;
    synth(B0, 0);
    __syncthreads();

    unsigned* cur = B0; unsigned* nxt = B1;
    for (int kbi = 0; kbi < KGL / 32; kbi++) {
        #pragma unroll
        for (int k8 = 0; k8 < 2; k8++) {
            unsigned af[4][4], bf[8][2];
            #pragma unroll
            for (int i = 0; i < 4; i++) {
                int r = wr + i * 16 + g;
                af[i][0] = cur[r * 20 + k8 * 8 + t4];
                af[i][1] = cur[(r + 8) * 20 + k8 * 8 + t4];
                af[i][2] = cur[r * 20 + k8 * 8 + t4 + 4];
                af[i][3] = cur[(r + 8) * 20 + k8 * 8 + t4 + 4];
            }
            #pragma unroll
            for (int j = 0; j < 8; j++) {
                int n = wc + j * 8 + g;
                bf[j][0] = cur[n * 20 + k8 * 8 + t4];
                bf[j][1] = cur[n * 20 + k8 * 8 + t4 + 4];
            }
            #pragma unroll
            for (int i = 0; i < 4; i++)
                #pragma unroll
                for (int j = 0; j < 8; j++)
                    mma_f16(acc[i][j], af[i], bf[j]);
        }
        if (kbi + 1 < KGL / 32) synth(nxt, (kbi + 1) * 32);
        __syncthreads();
        unsigned* tmp = cur; cur = nxt; nxt = tmp;
    }

    // ---- epilogue: relu; raw store; rowsums; Q01 colsums; mirror Q01^T ----
    float* rsm = (float*)smA;                    // [128][5]
    float* csm = (float*)(smA + 640);            // [128][2]
    unsigned* Tm = smA + 1024;                   // [128][66] uints (transposed Q01)
    __half* Th = (__half*)Tm;                    // half stride 132

    #pragma unroll
    for (int i = 0; i < 4; i++)
        #pragma unroll
        for (int j = 0; j < 8; j++)
            #pragma unroll
            for (int v = 0; v < 4; v++) acc[i][j][v] = fmaxf(acc[i][j][v], 0.0f);

    // rowsums (rows 0-127)
    #pragma unroll
    for (int i = 0; i < 4; i++) {
        float s0 = 0.0f, s1 = 0.0f;
        #pragma unroll
        for (int j = 0; j < 8; j++) {
            s0 += acc[i][j][0] + acc[i][j][1];
            s1 += acc[i][j][2] + acc[i][j][3];
        }
        s0 += __shfl_xor_sync(0xffffffffu, s0, 1);
        s0 += __shfl_xor_sync(0xffffffffu, s0, 2);
        s1 += __shfl_xor_sync(0xffffffffu, s1, 1);
        s1 += __shfl_xor_sync(0xffffffffu, s1, 2);
        if (t4 == 0) {
            rsm[(wr + i * 16 + g) * 5 + (wid & 3)] = s0;
            rsm[(wr + i * 16 + g + 8) * 5 + (wid & 3)] = s1;
        }
    }
    // colsums of Q01 (cols 128-255) + mirror stage
    if ((wid & 3) >= 2) {
        #pragma unroll
        for (int j = 0; j < 8; j++) {
            float c0s = 0.0f, c1s = 0.0f;
            #pragma unroll
            for (int i = 0; i < 4; i++) {
                c0s += acc[i][j][0] + acc[i][j][2];
                c1s += acc[i][j][1] + acc[i][j][3];
            }
            c0s += __shfl_xor_sync(0xffffffffu, c0s, 4);
            c0s += __shfl_xor_sync(0xffffffffu, c0s, 8);
            c0s += __shfl_xor_sync(0xffffffffu, c0s, 16);
            c1s += __shfl_xor_sync(0xffffffffu, c1s, 4);
            c1s += __shfl_xor_sync(0xffffffffu, c1s, 8);
            c1s += __shfl_xor_sync(0xffffffffu, c1s, 16);
            if (g == 0) {
                int c = (wc - 128) + j * 8 + t4 * 2;
                csm[c * 2 + (wid >> 2)]       = c0s;
                csm[(c + 1) * 2 + (wid >> 2)] = c1s;
            }
        }
        #pragma unroll
        for (int i = 0; i < 4; i++) {
            int r0 = wr + i * 16 + g, r1 = r0 + 8;
            #pragma unroll
            for (int j = 0; j < 8; j++) {
                int c = (wc - 128) + j * 8 + t4 * 2;
                Th[c * 132 + r0]       = __float2half(acc[i][j][0]);
                Th[(c + 1) * 132 + r0] = __float2half(acc[i][j][1]);
                Th[c * 132 + r1]       = __float2half(acc[i][j][2]);
                Th[(c + 1) * 132 + r1] = __float2half(acc[i][j][3]);
            }
        }
    }
    // direct raw store rows 0-127, all cols
    #pragma unroll
    for (int i = 0; i < 4; i++) {
        int r0 = wr + i * 16 + g, r1 = r0 + 8;
        #pragma unroll
        for (int j = 0; j < 8; j++) {
            int c0 = wc + j * 8 + t4 * 2;
            *(unsigned*)&Sb[(long)r0 * NN + c0] = pk2(acc[i][j][0], acc[i][j][1]);
            *(unsigned*)&Sb[(long)r1 * NN + c0] = pk2(acc[i][j][2], acc[i][j][3]);
        }
    }
    __syncthreads();
    // combine sums -> rsA
    if (tid < 128) {
        rsA[(long)bz * NN + tid] =
            rsm[tid*5] + rsm[tid*5+1] + rsm[tid*5+2] + rsm[tid*5+3];
    } else {
        int c = tid - 128;
        rsA[(long)bz * NN + 128 + c] = csm[c*2] + csm[c*2+1];
    }
    // mirror write: S[128+c][r] = T[c][r]   (rows 128-255, cols 0-127)
    #pragma unroll
    for (int it = 0; it < 32; it++) {
        int e = tid + it * 256;
        int rr = e >> 6, cc = e & 63;
        ((unsigned*)(Sb + (long)(128 + rr) * NN))[cc] = Tm[rr * 66 + cc];
    }
}

// ============ attention kernel B: Q11 only (rows x cols 128-255) ===============
#define BT_ST0   0
#define BT_ST1   2560
#define BT_SX    5120       // 128 x 65
#define BT_SR    13440      // 2048 floats
#define BT_SW    15488      // 2048 floats
#define BT_UINTS 17536
#define ATTB_BYTES (BT_UINTS * 4)

__global__ __launch_bounds__(256) void att_b_kernel(
    const float* __restrict__ x, const float* __restrict__ Wgl,
    const float* __restrict__ rinv, __half* __restrict__ S,
    float* __restrict__ rsB)
{
    extern __shared__ __align__(16) unsigned smB[];
    unsigned* sX = smB + BT_SX;
    float* sR = (float*)(smB + BT_SR);
    float* sW = (float*)(smB + BT_SW);

    const int tid = threadIdx.x;
    const int lane = tid & 31, wid = tid >> 5;
    const int g = lane >> 2, t4 = lane & 3;
    const int wr = (wid >> 2) * 64;            // {0,64}
    const int wc = (wid & 3) * 32;             // {0,32,64,96}
    const int bz = blockIdx.x;

    const float* xb = x + (long)bz * NN * DD;
    const float* rb = rinv + (long)bz * NN * HEADS;
    __half* Sb = S + (long)bz * NN * NN;

    const int myN = tid >> 3;                  // 0..31
    const int c4  = tid & 7;

    // stage x rows 128-255, rinv rows 128-255, Wgl
    #pragma unroll
    for (int it = 0; it < 16; it++) {
        int e = tid + it * 256, n = e >> 5, c = e & 31;
        float4 v = *(const float4*)&xb[(long)(128 + n) * DD + c * 4];
        sX[n * 65 + c * 2]     = pk2(v.x, v.y);
        sX[n * 65 + c * 2 + 1] = pk2(v.z, v.w);
    }
    #pragma unroll
    for (int it = 0; it < 2; it++)
        ((float4*)sR)[tid + it * 256] = ((const float4*)(rb + 128 * HEADS))[tid + it * 256];
    #pragma unroll
    for (int it = 0; it < 2; it++)
        ((float4*)sW)[tid + it * 256] = ((const float4*)Wgl)[tid + it * 256];
    __syncthreads();

    float acc[4][4][4] = {};

    auto synth = [&](unsigned* buf, int kb) {
        int h = kb >> 7;
        int dof = (kb & 127) + c4 * 4;
        float4 ws = *(const float4*)&sW[kb + c4 * 4];
        #pragma unroll
        for (int it = 0; it < 4; it++) {
            int n = myN + it * 32;             // 0..127 local
            float rn = sR[n * 16 + h];
            int base = n * 65 + (dof >> 1);
            unsigned x0 = sX[base], x1 = sX[base + 1];
            float2 a = __half22float2(*(__half2*)&x0);
            float2 b = __half22float2(*(__half2*)&x1);
            buf[n * 20 + c4 * 2]     = pk2(a.x * ws.x * rn, a.y * ws.y * rn);
            buf[n * 20 + c4 * 2 + 1] = pk2(b.x * ws.z * rn, b.y * ws.w * rn);
        }
    };

    unsigned* B0 = smB + BT_ST0;
    unsigned* B1 = smB + BT_ST1;
    synth(B0, 0);
    __syncthreads();

    unsigned* cur = B0; unsigned* nxt = B1;
    for (int kbi = 0; kbi < KGL / 32; kbi++) {
        #pragma unroll
        for (int k8 = 0; k8 < 2; k8++) {
            unsigned af[4][4], bf[4][2];
            #pragma unroll
            for (int i = 0; i < 4; i++) {
                int r = wr + i * 16 + g;
                af[i][0] = cur[r * 20 + k8 * 8 + t4];
                af[i][1] = cur[(r + 8) * 20 + k8 * 8 + t4];
                af[i][2] = cur[r * 20 + k8 * 8 + t4 + 4];
                af[i][3] = cur[(r + 8) * 20 + k8 * 8 + t4 + 4];
            }
            #pragma unroll
            for (int j = 0; j < 4; j++) {
                int n = wc + j * 8 + g;
                bf[j][0] = cur[n * 20 + k8 * 8 + t4];
                bf[j][1] = cur[n * 20 + k8 * 8 + t4 + 4];
            }
            #pragma unroll
            for (int i = 0; i < 4; i++)
                #pragma unroll
                for (int j = 0; j < 4; j++)
                    mma_f16(acc[i][j], af[i], bf[j]);
        }
        if (kbi + 1 < KGL / 32) synth(nxt, (kbi + 1) * 32);
        __syncthreads();
        unsigned* tmp = cur; cur = nxt; nxt = tmp;
    }

    // ---- epilogue: relu; Q11 rowsums -> rsB; raw store ----
    float* rsm = (float*)smB;                   // [128][5]
    #pragma unroll
    for (int i = 0; i < 4; i++)
        #pragma unroll
        for (int j = 0; j < 4; j++)
            #pragma unroll
            for (int v = 0; v < 4; v++) acc[i][j][v] = fmaxf(acc[i][j][v], 0.0f);

    #pragma unroll
    for (int i = 0; i < 4; i++) {
        float s0 = 0.0f, s1 = 0.0f;
        #pragma unroll
        for (int j = 0; j < 4; j++) {
            s0 += acc[i][j][0] + acc[i][j][1];
            s1 += acc[i][j][2] + acc[i][j][3];
        }
        s0 += __shfl_xor_sync(0xffffffffu, s0, 1);
        s0 += __shfl_xor_sync(0xffffffffu, s0, 2);
        s1 += __shfl_xor_sync(0xffffffffu, s1, 1);
        s1 += __shfl_xor_sync(0xffffffffu, s1, 2);
        if (t4 == 0) {
            rsm[(wr + i * 16 + g) * 5 + (wid & 3)] = s0;
            rsm[(wr + i * 16 + g + 8) * 5 + (wid & 3)] = s1;
        }
    }
    #pragma unroll
    for (int i = 0; i < 4; i++) {
        int r0 = wr + i * 16 + g, r1 = r0 + 8;
        #pragma unroll
        for (int j = 0; j < 4; j++) {
            int c0 = wc + j * 8 + t4 * 2;
            *(unsigned*)&Sb[(long)(128 + r0) * NN + 128 + c0] = pk2(acc[i][j][0], acc[i][j][1]);
            *(unsigned*)&Sb[(long)(128 + r1) * NN + 128 + c0] = pk2(acc[i][j][2], acc[i][j][3]);
        }
    }
    __syncthreads();
    if (tid < 128)
        rsB[(long)bz * NN + 128 + tid] =
            rsm[tid*5] + rsm[tid*5+1] + rsm[tid*5+2] + rsm[tid*5+3];
}

// ---------------- inv = wt / (rowsum + eps) -----------------------------------
__global__ __launch_bounds__(256) void inv_kernel(
    const float* __restrict__ rsA, const float* __restrict__ rsB, float* __restrict__ inv)
{
    int bz = blockIdx.x, n = threadIdx.x;
    int t = bz >> 5;
    float wt = 0.7f * powf(SKIPW, (float)(T_STEPS - 1 - t));
    float rs = rsA[(long)bz * NN + n];
    if (n >= 128) rs += rsB[(long)bz * NN + n];
    inv[(long)bz * NN + n] = wt / (rs + EPSV);
}

// ------- A = 0.3^16*sup + sum_t raw_t * inv_t[n] (fp16 in, fp32 out) -----------
__global__ __launch_bounds__(256) void reduce_kernel(
    const __half* __restrict__ S, const float* __restrict__ inv,
    const float* __restrict__ sup, float* __restrict__ A)
{
    long i4 = (long)blockIdx.x * 256 + threadIdx.x;
    const uint2* S2 = (const uint2*)S;
    const float4* P4 = (const float4*)sup;
    float4* A4 = (float4*)A;
    int b = (int)(i4 >> 14);
    long rem = i4 & 16383;
    int n = (int)(rem >> 6);
    const float k16 = 4.3046721e-8f;
    float4 p = P4[i4];
    float4 a = make_float4(p.x * k16, p.y * k16, p.z * k16, p.w * k16);
    #pragma unroll
    for (int t = 0; t < T_STEPS; t++) {
        int bz = t * BATCH + b;
        uint2 v = S2[(((long)bz) << 14) + rem];
        float iv = inv[(long)bz * NN + n];
        float2 v01 = __half22float2(*(__half2*)&v.x);
        float2 v23 = __half22float2(*(__half2*)&v.y);
        a.x += v01.x * iv; a.y += v01.y * iv;
        a.z += v23.x * iv; a.w += v23.y * iv;
    }
    A4[i4] = a;
}

// ------- prep: fold Wa/ba into gate weights; output fp16 (N,K) blocks ----------
__global__ void prep_kernel(
    const float* __restrict__ Wa, const float* __restrict__ Wr,
    const float* __restrict__ Wz, const float* __restrict__ Wh,
    const float* __restrict__ ba, const float* __restrict__ br,
    const float* __restrict__ bz, const float* __restrict__ bh,
    __half* __restrict__ Brz, __half* __restrict__ Bh_,
    float* __restrict__ brz2, float* __restrict__ bh2)
{
    int idx = blockIdx.x * blockDim.x + threadIdx.x;
    if (idx < 65536) {
        int n = idx >> 8, k = idx & 255, np = n & 127;
        const float* W = (n < 128) ? Wr : Wz;
        float v;
        if (k < 128) {
            v = 0.0f;
            for (int d = 0; d < 128; d++) v += Wa[k * 128 + d] * W[d * 128 + np];
        } else v = W[k * 128 + np];
        Brz[n * 256 + k] = __float2half(v);
    } else if (idx < 98304) {
        int e = idx - 65536, n = e >> 8, k = e & 255;
        float v;
        if (k < 128) {
            v = 0.0f;
            for (int d = 0; d < 128; d++) v += Wa[k * 128 + d] * Wh[d * 128 + n];
        } else v = Wh[k * 128 + n];
        Bh_[n * 256 + k] = __float2half(v);
    } else if (idx < 98560) {
        int n = idx - 98304, np = n & 127;
        const float* W = (n < 128) ? Wr : Wz;
        float v = (n < 128) ? br[np] : bz[np];
        for (int d = 0; d < 128; d++) v += ba[d] * W[d * 128 + np];
        brz2[n] = v;
    } else if (idx < 98688) {
        int n = idx - 98560;
        float v = bh[n];
        for (int d = 0; d < 128; d++) v += ba[d] * Wh[d * 128 + n];
        bh2[n] = v;
    }
}

// ---------------- per-batch (N,D) -> (D,N) transpose ---------------------------
__global__ void transpose_k(const float* __restrict__ src, float* __restrict__ dst)
{
    __shared__ float tile[32][33];
    int b = blockIdx.z;
    int n0 = blockIdx.x * 32, d0 = blockIdx.y * 32;
    const float* s = src + (long)b * NN * DD;
    float* o = dst + (long)b * NN * DD;
    #pragma unroll
    for (int k = 0; k < 4; k++)
        tile[threadIdx.y + k * 8][threadIdx.x] =
            s[(long)(n0 + threadIdx.y + k * 8) * DD + d0 + threadIdx.x];
    __syncthreads();
    #pragma unroll
    for (int k = 0; k < 4; k++)
        o[(long)(d0 + threadIdx.y + k * 8) * NN + n0 + threadIdx.x] =
            tile[threadIdx.x][threadIdx.y + k * 8];
}

// ---------------- fully fused GGNN step (256 threads, 8 warps) -----------------
__global__ __launch_bounds__(256) void ggnn_step(
    const float* __restrict__ A, const float* __restrict__ h_in,
    const float* __restrict__ hT_in,
    const __half* __restrict__ Brz, const float* __restrict__ brz,
    const __half* __restrict__ Bh, const float* __restrict__ bh,
    float* __restrict__ h_out, float* __restrict__ hT_out)
{
    extern __shared__ __align__(16) unsigned smG[];
    unsigned* sAm = smG;                  // [64][68]
    unsigned* sH  = sAm + 64 * 68;        // [64][68]
    unsigned* sRZ = sH  + 64 * 68;        // [64][132]
    unsigned* sB  = sRZ + 64 * 132;       // stream buffer (max [256][20])
    unsigned* sA1 = sB  + 256 * 20;       // [64][20]

    const int tid = threadIdx.x, lane = tid & 31, wid = tid >> 5;
    const int g = lane >> 2, t4 = lane & 3;
    const int b = blockIdx.y, r0 = blockIdx.x * 64;
    const int wr = (wid >> 1) * 16;
    const int wcn = (wid & 1) * 64;

    const float* Ab  = A + (long)b * NN * NN;
    const float* hb  = h_in + (long)b * NN * DD;
    const float* hTb = hT_in + (long)b * NN * DD;
    float* hob  = h_out + (long)b * NN * DD;
    float* hTob = hT_out + (long)b * NN * DD;

    #pragma unroll
    for (int i = 0; i < 8; i++) {
        int e = tid + i * 256;
        int r = e >> 5, c4 = e & 31;
        float4 v = *(const float4*)&hb[(long)(r0 + r) * DD + c4 * 4];
        *(uint2*)&sH[r * 68 + c4 * 2] = pk4(v);
    }

    // ================= Phase 1: am = A @ h =================
    float acc1[8][4] = {};
    for (int kb = 0; kb < 256; kb += 32) {
        #pragma unroll
        for (int i = 0; i < 2; i++) {
            int e = tid + i * 256;
            int r = e >> 3, c4 = e & 7;
            float4 v = *(const float4*)&Ab[(long)(r0 + r) * NN + kb + c4 * 4];
            *(uint2*)&sA1[r * 20 + c4 * 2] = pk4(v);
        }
        #pragma unroll
        for (int i = 0; i < 4; i++) {
            int e = tid + i * 256;
            int d = e >> 3, nq = e & 7;
            float4 v = *(const float4*)&hTb[(long)d * NN + kb + nq * 4];
            *(uint2*)&sB[d * 18 + nq * 2] = pk4(v);
        }
        __syncthreads();
        #pragma unroll
        for (int k8 = 0; k8 < 2; k8++) {
            unsigned af[4], bf[8][2];
            int row = wr + g;
            af[0] = sA1[row * 20 + k8 * 8 + t4];
            af[1] = sA1[(row + 8) * 20 + k8 * 8 + t4];
            af[2] = sA1[row * 20 + k8 * 8 + t4 + 4];
            af[3] = sA1[(row + 8) * 20 + k8 * 8 + t4 + 4];
            #pragma unroll
            for (int j = 0; j < 8; j++) {
                int n = wcn + j * 8 + g;
                bf[j][0] = sB[n * 18 + k8 * 8 + t4];
                bf[j][1] = sB[n * 18 + k8 * 8 + t4 + 4];
            }
            #pragma unroll
            for (int j = 0; j < 8; j++)
                mma_f16(acc1[j], af, bf[j]);
        }
        __syncthreads();
    }
    {
        int row = wr + g;
        #pragma unroll
        for (int j = 0; j < 8; j++) {
            int colp = ((wcn + j * 8) >> 1) + t4;
            sAm[row * 68 + colp]       = pk2(acc1[j][0], acc1[j][1]);
            sAm[(row + 8) * 68 + colp] = pk2(acc1[j][2], acc1[j][3]);
        }
    }
    __syncthreads();

    // ================= Phase 2: [r|z] = sigmoid([am|h] @ Brz + brz2) ==========
    {
        const int wc2 = (wid & 1) * 128;
        float acc2[16][4] = {};
        for (int kb = 0; kb < 256; kb += 32) {
            #pragma unroll
            for (int i = 0; i < 4; i++) {
                int e = tid + i * 256;
                int n = e >> 2, c8 = e & 3;
                uint4 v = *(const uint4*)(Brz + (long)n * 256 + kb + c8 * 8);
                *(uint4*)&sB[n * 20 + c8 * 4] = v;
            }
            __syncthreads();
            const unsigned* src = (kb < 128) ? sAm : sH;
            #pragma unroll
            for (int k8 = 0; k8 < 2; k8++) {
                int pb = ((kb & 127) >> 1) + k8 * 8;
                unsigned af[4], bf[16][2];
                int row = wr + g;
                af[0] = src[row * 68 + pb + t4];
                af[1] = src[(row + 8) * 68 + pb + t4];
                af[2] = src[row * 68 + pb + t4 + 4];
                af[3] = src[(row + 8) * 68 + pb + t4 + 4];
                #pragma unroll
                for (int j = 0; j < 16; j++) {
                    int n = wc2 + j * 8 + g;
                    bf[j][0] = sB[n * 20 + k8 * 8 + t4];
                    bf[j][1] = sB[n * 20 + k8 * 8 + t4 + 4];
                }
                #pragma unroll
                for (int j = 0; j < 16; j++)
                    mma_f16(acc2[j], af, bf[j]);
            }
            __syncthreads();
        }
        {
            int row = wr + g;
            #pragma unroll
            for (int j = 0; j < 16; j++) {
                int col = wc2 + j * 8 + 2 * t4;
                float b0 = brz[col], b1 = brz[col + 1];
                float v00 = 1.0f / (1.0f + expf(-(acc2[j][0] + b0)));
                float v01 = 1.0f / (1.0f + expf(-(acc2[j][1] + b1)));
                float v10 = 1.0f / (1.0f + expf(-(acc2[j][2] + b0)));
                float v11 = 1.0f / (1.0f + expf(-(acc2[j][3] + b1)));
                sRZ[row * 132 + (col >> 1)]       = pk2(v00, v01);
                sRZ[(row + 8) * 132 + (col >> 1)] = pk2(v10, v11);
            }
        }
    }
    __syncthreads();

    // ================= Phase 3: GRU candidate + update ========================
    float acc3[8][4] = {};
    for (int kb = 0; kb < 256; kb += 32) {
        #pragma unroll
        for (int i = 0; i < 2; i++) {
            int e = tid + i * 256;
            int n = e >> 2, c8 = e & 3;
            uint4 v = *(const uint4*)(Bh + (long)n * 256 + kb + c8 * 8);
            *(uint4*)&sB[n * 20 + c8 * 4] = v;
        }
        __syncthreads();
        const bool lowK = (kb < 128);
        #pragma unroll
        for (int k8 = 0; k8 < 2; k8++) {
            int pb = ((kb & 127) >> 1) + k8 * 8;
            unsigned af[4], bf[8][2];
            int row = wr + g;
            if (lowK) {
                af[0] = sAm[row * 68 + pb + t4];
                af[1] = sAm[(row + 8) * 68 + pb + t4];
                af[2] = sAm[row * 68 + pb + t4 + 4];
                af[3] = sAm[(row + 8) * 68 + pb + t4 + 4];
            } else {
                af[0] = hmul2u(sRZ[row * 132 + pb + t4],       sH[row * 68 + pb + t4]);
                af[1] = hmul2u(sRZ[(row + 8) * 132 + pb + t4], sH[(row + 8) * 68 + pb + t4]);
                af[2] = hmul2u(sRZ[row * 132 + pb + t4 + 4],       sH[row * 68 + pb + t4 + 4]);
                af[3] = hmul2u(sRZ[(row + 8) * 132 + pb + t4 + 4], sH[(row + 8) * 68 + pb + t4 + 4]);
            }
            #pragma unroll
            for (int j = 0; j < 8; j++) {
                int n = wcn + j * 8 + g;
                bf[j][0] = sB[n * 20 + k8 * 8 + t4];
                bf[j][1] = sB[n * 20 + k8 * 8 + t4 + 4];
            }
            #pragma unroll
            for (int j = 0; j < 8; j++)
                mma_f16(acc3[j], af, bf[j]);
        }
        __syncthreads();
    }
    {
        int row = wr + g;
        int gr0 = r0 + row, gr1 = gr0 + 8;
        #pragma unroll
        for (int j = 0; j < 8; j++) {
            int col = wcn + j * 8 + 2 * t4;
            float bb0 = bh[col], bb1 = bh[col + 1];
            unsigned z0u = sRZ[row * 132 + 64 + (col >> 1)];
            unsigned z1u = sRZ[(row + 8) * 132 + 64 + (col >> 1)];
            float2 z0 = __half22float2(*(__half2*)&z0u);
            float2 z1 = __half22float2(*(__half2*)&z1u);
            float2 ho0 = *(const float2*)&hb[(long)gr0 * DD + col];
            float2 ho1 = *(const float2*)&hb[(long)gr1 * DD + col];
            float t00 = tanhf(acc3[j][0] + bb0);
            float t01 = tanhf(acc3[j][1] + bb1);
            float t10 = tanhf(acc3[j][2] + bb0);
            float t11 = tanhf(acc3[j][3] + bb1);
            float o00 = (1.0f - z0.x) * ho0.x + z0.x * t00;
            float o01 = (1.0f - z0.y) * ho0.y + z0.y * t01;
            float o10 = (1.0f - z1.x) * ho1.x + z1.x * t10;
            float o11 = (1.0f - z1.y) * ho1.y + z1.y * t11;
            *(float2*)&hob[(long)gr0 * DD + col] = make_float2(o00, o01);
            *(float2*)&hob[(long)gr1 * DD + col] = make_float2(o10, o11);
            hTob[(long)col * NN + gr0] = o00;
            hTob[(long)(col + 1) * NN + gr0] = o01;
            hTob[(long)col * NN + gr1] = o10;
            hTob[(long)(col + 1) * NN + gr1] = o11;
        }
    }
}

// ---------------- final classifier --------------------------------------------
__global__ __launch_bounds__(256) void fc_kernel(
    const float* __restrict__ h, const float* __restrict__ W,
    const float* __restrict__ bfc, float* __restrict__ out)
{
    int b = blockIdx.x, c = blockIdx.y;
    float s = 0.0f;
    for (int i = threadIdx.x; i < NN * DD; i += 256)
        s += h[(long)b * NN * DD + i] * W[(long)i * NCLS + c];
    #pragma unroll
    for (int o = 16; o; o >>= 1) s += __shfl_xor_sync(0xffffffffu, s, o);
    __shared__ float sh[8];
    if ((threadIdx.x & 31) == 0) sh[threadIdx.x >> 5] = s;
    __syncthreads();
    if (threadIdx.x == 0) {
        float t = 0.0f;
        for (int w = 0; w < 8; w++) t += sh[w];
        out[b * NCLS + c] = t + bfc[c];
    }
}

// ---------------- orchestration -----------------------------------------------
extern "C" void kernel_launch(void* const* d_in, const int* in_sizes, int n_in,
                              void* d_out, int out_size)
{
    const float* x        = (const float*)d_in[0];
    const float* supports = (const float*)d_in[1];
    const float* Wgl      = (const float*)d_in[2];
    const float* Wa       = (const float*)d_in[3];
    const float* ba       = (const float*)d_in[4];
    const float* Wr       = (const float*)d_in[5];
    const float* br       = (const float*)d_in[6];
    const float* Wz       = (const float*)d_in[7];
    const float* bz       = (const float*)d_in[8];
    const float* Wh       = (const float*)d_in[9];
    const float* bh       = (const float*)d_in[10];
    const float* Wfc      = (const float*)d_in[11];
    const float* bfc      = (const float*)d_in[12];
    float* out            = (float*)d_out;

    float *A0, *h0, *h1, *hT0, *hT1, *xT, *ri, *rsA, *rsB, *inv, *brz2, *bh2;
    __half *S, *Brz, *Bh_;
    cudaGetSymbolAddress((void**)&S,    g_S);
    cudaGetSymbolAddress((void**)&A0,   g_A0);
    cudaGetSymbolAddress((void**)&h0,   g_h0);
    cudaGetSymbolAddress((void**)&h1,   g_h1);
    cudaGetSymbolAddress((void**)&hT0,  g_hT0);
    cudaGetSymbolAddress((void**)&hT1,  g_hT1);
    cudaGetSymbolAddress((void**)&xT,   g_xT);
    cudaGetSymbolAddress((void**)&ri,   g_ri);
    cudaGetSymbolAddress((void**)&rsA,  g_rsA);
    cudaGetSymbolAddress((void**)&rsB,  g_rsB);
    cudaGetSymbolAddress((void**)&inv,  g_inv);
    cudaGetSymbolAddress((void**)&Brz,  g_Brz_h);
    cudaGetSymbolAddress((void**)&Bh_,  g_Bh_h);
    cudaGetSymbolAddress((void**)&brz2, g_brz2);
    cudaGetSymbolAddress((void**)&bh2,  g_bh2);

    const int GGNN_SMEM = (64*68 + 64*68 + 64*132 + 256*20 + 64*20) * 4;  // 94208
    static bool attr_set = false;
    if (!attr_set) {
        cudaFuncSetAttribute(att_a_kernel, cudaFuncAttributeMaxDynamicSharedMemorySize,
                             ATTA_BYTES);
        cudaFuncSetAttribute(att_b_kernel, cudaFuncAttributeMaxDynamicSharedMemorySize,
                             ATTB_BYTES);
        cudaFuncSetAttribute(ggnn_step, cudaFuncAttributeMaxDynamicSharedMemorySize,
                             GGNN_SMEM);
        attr_set = true;
    }

    prep_kernel<<<386, 256>>>(Wa, Wr, Wz, Wh, ba, br, bz, bh, Brz, Bh_, brz2, bh2);

    // ---- attention: symmetric 3-quadrant scheme, raw fp16 + deferred norm ----
    rinv_kernel<<<T_STEPS * BATCH * NN, 128>>>(x, Wgl, ri);
    att_a_kernel<<<T_STEPS * BATCH, 256, ATTA_BYTES>>>(x, Wgl, ri, S, rsA);
    att_b_kernel<<<T_STEPS * BATCH, 256, ATTB_BYTES>>>(x, Wgl, ri, S, rsB);
    inv_kernel<<<T_STEPS * BATCH, 256>>>(rsA, rsB, inv);
    reduce_kernel<<<(BATCH * NN * NN / 4) / 256, 256>>>(S, inv, supports, A0);

    // ---- GGNN for last timestep only, one fused kernel per step ----
    const float* xt = x + (long)(T_STEPS - 1) * BATCH * NN * DD;
    transpose_k<<<dim3(8, 4, BATCH), dim3(32, 8)>>>(xt, xT);

    const float* hp  = xt;
    const float* hpT = xT;
    float* hn  = h0;
    float* hnT = hT0;
    for (int s = 0; s < GSTEPS; s++) {
        ggnn_step<<<dim3(4, BATCH), 256, GGNN_SMEM>>>(
            A0, hp, hpT, Brz, brz2, Bh_, bh2, hn, hnT);
        hp = hn; hpT = hnT;
        hn  = (hn == h0) ? h1 : h0;
        hnT = (hnT == hT0) ? hT1 : hT0;
    }

    fc_kernel<<<dim3(BATCH, NCLS), 256>>>(hp, Wfc, bfc, out);
    (void)in_sizes; (void)n_in; (void)out_size;
}